// round 12
// baseline (speedup 1.0000x reference)
#include <cuda_runtime.h>
#include <cuda_fp16.h>

typedef unsigned int u32;
typedef unsigned long long u64;

// ---------------- problem constants ----------------
#define BB 4
#define LL 2048
#define DM 1024
#define NH 16
#define MR 8192
#define N3 3072

// ---------------- scratch (device globals; allocation is forbidden) ----------------
__device__ float g_qkv[(size_t)MR * N3];
__device__ float g_prj[(size_t)MR * DM];
__device__ __half g_xhi[(size_t)MR * DM],  g_xlo[(size_t)MR * DM];
__device__ __half g_whi[(size_t)N3 * DM],  g_wlo[(size_t)N3 * DM];
__device__ __half g_wohi[(size_t)DM * DM], g_wolo[(size_t)DM * DM];
__device__ __half g_qhi[(size_t)MR * DM],  g_qlo[(size_t)MR * DM];
__device__ __half g_khi[(size_t)MR * DM],  g_klo[(size_t)MR * DM];
__device__ __half g_ahi[(size_t)MR * DM],  g_alo[(size_t)MR * DM];
__device__ __half g_vthi[(size_t)BB * NH * 64 * LL], g_vtlo[(size_t)BB * NH * 64 * LL];

// ---------------- portable PTX helpers ----------------
__device__ __forceinline__ u32 smem_u32(const void* p) {
    u32 a;
    asm("{ .reg .u64 t; cvta.to.shared.u64 t, %1; cvt.u32.u64 %0, t; }" : "=r"(a) : "l"(p));
    return a;
}
__device__ __forceinline__ void ldsm4(u32& r0, u32& r1, u32& r2, u32& r3, u32 a) {
    asm volatile("ldmatrix.sync.aligned.m8n8.x4.shared.b16 {%0,%1,%2,%3},[%4];"
                 : "=r"(r0), "=r"(r1), "=r"(r2), "=r"(r3) : "r"(a));
}
__device__ __forceinline__ void ldsm2(u32& r0, u32& r1, u32 a) {
    asm volatile("ldmatrix.sync.aligned.m8n8.x2.shared.b16 {%0,%1},[%2];"
                 : "=r"(r0), "=r"(r1) : "r"(a));
}
__device__ __forceinline__ void mma16(float* c, const u32* a, const u32* b) {
    asm volatile("mma.sync.aligned.m16n8k16.row.col.f32.f16.f16.f32 "
                 "{%0,%1,%2,%3},{%4,%5,%6,%7},{%8,%9},{%0,%1,%2,%3};"
                 : "+f"(c[0]), "+f"(c[1]), "+f"(c[2]), "+f"(c[3])
                 : "r"(a[0]), "r"(a[1]), "r"(a[2]), "r"(a[3]), "r"(b[0]), "r"(b[1]));
}
__device__ __forceinline__ float ex2f(float x) {
    float y; asm("ex2.approx.f32 %0,%1;" : "=f"(y) : "f"(x)); return y;
}
__device__ __forceinline__ u32 h2pk(float a, float b) {
    __half2 t = __float22half2_rn(make_float2(a, b));
    return *(u32*)&t;
}
#define CPA16(d, s) asm volatile("cp.async.cg.shared.global [%0],[%1],16;" :: "r"(d), "l"(s) : "memory")
#define CPC()       asm volatile("cp.async.commit_group;" ::: "memory")
#define CPW(n)      asm volatile("cp.async.wait_group %0;" :: "n"(n) : "memory")

// =====================================================================
// fp32 -> fp16 hi/lo planar split
// =====================================================================
__global__ __launch_bounds__(256) void conv_hilo(
    const float* __restrict__ src, __half* __restrict__ hi,
    __half* __restrict__ lo, long n4)
{
    long i = (long)blockIdx.x * 256 + threadIdx.x;
    if (i >= n4) return;
    float4 v = ((const float4*)src)[i];
    float f[4] = { v.x, v.y, v.z, v.w };
    __half h[4], l[4];
#pragma unroll
    for (int e = 0; e < 4; e++) {
        h[e] = __float2half_rn(f[e]);
        l[e] = __float2half_rn(f[e] - __half2float(h[e]));
    }
    ((uint2*)hi)[i] = *(uint2*)h;
    ((uint2*)lo)[i] = *(uint2*)l;
}

// =====================================================================
// HMMA TN GEMM, fp16 hi/lo (3 products): C = A B^T + bias, fp32 out.
// 128x128 tile, 256 thr, K-chunk 32, double-buffered, 2 CTAs/SM.
// RACE-SAFE loop: sync BEFORE issuing the next prefetch, so laggard
// warps' reads of the other buffer (chunk c-1) are ordered first.
// =====================================================================
#define GSTR 40
#define GPL  5120
#define GBUF 20480
#define GM_SMEM (2 * GBUF * 2)

__global__ __launch_bounds__(256, 2) void gemm_mma(
    const __half* __restrict__ Ahi, const __half* __restrict__ Alo,
    const __half* __restrict__ Bhi, const __half* __restrict__ Blo,
    const float* __restrict__ bias, float* __restrict__ C, int N, int K)
{
    extern __shared__ __half sh[];
    const u32 sb = smem_u32(sh);
    const int tid = threadIdx.x, w = tid >> 5, lane = tid & 31;
    const int bm = blockIdx.y * 128, bn = blockIdx.x * 128;
    const int wm = (w >> 2) * 64, wn = (w & 3) * 32;

    float acc[4][4][4];
#pragma unroll
    for (int mt = 0; mt < 4; mt++)
#pragma unroll
        for (int nt = 0; nt < 4; nt++)
#pragma unroll
            for (int r = 0; r < 4; r++) acc[mt][nt][r] = 0.f;

    const int pl = tid >> 6, lu = tid & 63, ls = lu & 3, lr0 = lu >> 2;
    const __half* lbase = ((pl == 0) ? Ahi : (pl == 1) ? Alo : (pl == 2) ? Bhi : Blo)
                          + (long)((pl < 2 ? bm : bn) + lr0) * K + ls * 8;
    const u32 ldst0 = (u32)((pl * GPL + lr0 * GSTR + ls * 8) * 2);
    const long lrowstride = (long)16 * K;

    const int nch = K / 32;
#pragma unroll
    for (int it = 0; it < 8; it++) CPA16(sb + ldst0 + it * (16 * GSTR * 2), lbase + it * lrowstride);
    CPC();

    for (int c = 0; c < nch; c++) {
        CPW(0);
        __syncthreads();   // orders compute(c-1) reads before prefetch(c+1) writes
        if (c + 1 < nch) {
            u32 bo = (u32)(((c + 1) & 1) * GBUF * 2);
            const __half* src = lbase + (c + 1) * 32;
#pragma unroll
            for (int it = 0; it < 8; it++) CPA16(sb + bo + ldst0 + it * (16 * GSTR * 2), src + it * lrowstride);
            CPC();
        }
        u32 base = sb + (u32)((c & 1) * GBUF * 2);
#pragma unroll
        for (int ks = 0; ks < 2; ks++) {
            u32 ah[4][4], al[4][4], bh[4][2], bl[4][2];
#pragma unroll
            for (int mt = 0; mt < 4; mt++) {
                u32 ra = base + (u32)(((wm + mt * 16 + (lane & 15)) * GSTR +
                                       ks * 16 + ((lane >> 4) & 1) * 8) * 2);
                ldsm4(ah[mt][0], ah[mt][1], ah[mt][2], ah[mt][3], ra);
                ldsm4(al[mt][0], al[mt][1], al[mt][2], al[mt][3], ra + GPL * 2);
            }
#pragma unroll
            for (int nt = 0; nt < 4; nt++) {
                u32 rb = base + (u32)((2 * GPL + (wn + nt * 8 + (lane & 7)) * GSTR +
                                       ks * 16 + ((lane >> 3) & 1) * 8) * 2);
                ldsm2(bh[nt][0], bh[nt][1], rb);
                ldsm2(bl[nt][0], bl[nt][1], rb + GPL * 2);
            }
#pragma unroll
            for (int mt = 0; mt < 4; mt++)
#pragma unroll
                for (int nt = 0; nt < 4; nt++) {
                    mma16(acc[mt][nt], ah[mt], bh[nt]);
                    mma16(acc[mt][nt], ah[mt], bl[nt]);
                    mma16(acc[mt][nt], al[mt], bh[nt]);
                }
        }
    }
    // epilogue
#pragma unroll
    for (int mt = 0; mt < 4; mt++) {
        int r0 = bm + wm + mt * 16 + (lane >> 2);
#pragma unroll
        for (int nt = 0; nt < 4; nt++) {
            int cb = bn + wn + nt * 8 + 2 * (lane & 3);
            float2 bv = *(const float2*)(bias + cb);
            float2 o0 = make_float2(acc[mt][nt][0] + bv.x, acc[mt][nt][1] + bv.y);
            float2 o1 = make_float2(acc[mt][nt][2] + bv.x, acc[mt][nt][3] + bv.y);
            *(float2*)(C + (long)r0 * N + cb) = o0;
            *(float2*)(C + (long)(r0 + 8) * N + cb) = o1;
        }
    }
}

// =====================================================================
// q/k RMS norm -> fp16 hi/lo. q folds g*4*log2(e)/||q||, k folds g*32/||k||
// =====================================================================
__global__ __launch_bounds__(256) void qk_norm(
    const float* __restrict__ qkv,
    const float* __restrict__ gq, const float* __restrict__ gk,
    __half* __restrict__ qhi, __half* __restrict__ qlo,
    __half* __restrict__ khi, __half* __restrict__ klo)
{
    long row = blockIdx.x;
    const float* p = qkv + row * (long)N3;
    int c = threadIdx.x * 4;
    float4 q4 = *(const float4*)(p + c);
    float4 k4 = *(const float4*)(p + DM + c);
    float sq = q4.x * q4.x + q4.y * q4.y + q4.z * q4.z + q4.w * q4.w;
    float sk = k4.x * k4.x + k4.y * k4.y + k4.z * k4.z + k4.w * k4.w;
#pragma unroll
    for (int m = 16; m; m >>= 1) {
        sq += __shfl_xor_sync(0xffffffffu, sq, m);
        sk += __shfl_xor_sync(0xffffffffu, sk, m);
    }
    __shared__ float2 ws[8];
    __shared__ float2 fac;
    int w = threadIdx.x >> 5;
    if ((threadIdx.x & 31) == 0) ws[w] = make_float2(sq, sk);
    __syncthreads();
    if (threadIdx.x == 0) {
        float a = 0.f, bsum = 0.f;
#pragma unroll
        for (int i = 0; i < 8; i++) { a += ws[i].x; bsum += ws[i].y; }
        fac = make_float2(5.770780163555851f / fmaxf(sqrtf(a), 1e-12f),   // 4*log2(e)
                          32.0f / fmaxf(sqrtf(bsum), 1e-12f));
    }
    __syncthreads();
    float fq = fac.x, fk = fac.y;
    float4 gq4 = *(const float4*)(gq + c);
    float4 gk4 = *(const float4*)(gk + c);
    float qs[4] = { q4.x * fq * gq4.x, q4.y * fq * gq4.y, q4.z * fq * gq4.z, q4.w * fq * gq4.w };
    float ks[4] = { k4.x * fk * gk4.x, k4.y * fk * gk4.y, k4.z * fk * gk4.z, k4.w * fk * gk4.w };
    __half qh[4], ql[4], kh[4], kl[4];
#pragma unroll
    for (int e = 0; e < 4; e++) {
        qh[e] = __float2half_rn(qs[e]); ql[e] = __float2half_rn(qs[e] - __half2float(qh[e]));
        kh[e] = __float2half_rn(ks[e]); kl[e] = __float2half_rn(ks[e] - __half2float(kh[e]));
    }
    long o = row * (long)DM + c;
    *(uint2*)(qhi + o) = *(uint2*)qh;  *(uint2*)(qlo + o) = *(uint2*)ql;
    *(uint2*)(khi + o) = *(uint2*)kh;  *(uint2*)(klo + o) = *(uint2*)kl;
}

// =====================================================================
// V transpose: qkv v-part (b,l,h*64+d) fp32 -> fp16 hi/lo [(bh*64+d)][l]
// =====================================================================
#define VT_STR 136
__global__ __launch_bounds__(256) void v_trans(
    const float* __restrict__ qkv, __half* __restrict__ vthi, __half* __restrict__ vtlo)
{
    __shared__ __half shi[64 * VT_STR], slo[64 * VT_STR];
    int bh = blockIdx.y, b = bh >> 4, h = bh & 15;
    int l0 = blockIdx.x * 128;
    int tid = threadIdx.x;
#pragma unroll
    for (int it = 0; it < 8; it++) {
        int idx = it * 256 + tid;
        int l = idx >> 4, d4 = (idx & 15) * 4;
        float4 v = *(const float4*)(qkv + ((long)(b * LL + l0 + l)) * N3 + 2 * DM + h * 64 + d4);
        float f[4] = { v.x, v.y, v.z, v.w };
#pragma unroll
        for (int e = 0; e < 4; e++) {
            __half hv = __float2half_rn(f[e]);
            __half lv = __float2half_rn(f[e] - __half2float(hv));
            shi[(d4 + e) * VT_STR + l] = hv;
            slo[(d4 + e) * VT_STR + l] = lv;
        }
    }
    __syncthreads();
#pragma unroll
    for (int it = 0; it < 8; it++) {
        int i = it * 256 + tid;
        int pl = i >> 10, j = i & 1023;
        int d = j >> 4, s = j & 15;
        uint4 v = *(uint4*)&((pl ? slo : shi)[d * VT_STR + s * 8]);
        *(uint4*)((pl ? vtlo : vthi) + ((long)bh * 64 + d) * LL + l0 + s * 8) = v;
    }
}

// =====================================================================
// HMMA flash attention, register-resident P (FA2 style).
// Block = (128-q tile, bh). 8 warps = 4 row-groups x 2 key-halves.
// Warp: 32 q-rows x 32 keys (S), full d=64 for its key-slice (PV).
// S: 3 hi/lo products. PV: P fp16 (from registers) x V hi/lo = 2 products.
// smem (halves): QHI 0, QLO 9216, KV0 18432, KV1 36864
//   (per buf: Khi +0, Klo +4608, Vhi +9216, Vlo +13824)
// floats: rmax[2][2][128] @ byte 110592, lsum[2][128] after it.
// O-combine region (floats, stride 68) reuses KV0 space @ byte 36864.
// =====================================================================
#define AKV0 18432
#define AKV1 36864
#define ARED_B 110592
#define AT_SMEM (110592 + 3072)

__global__ __launch_bounds__(256) void attn_mma(
    const __half* __restrict__ qhi, const __half* __restrict__ qlo,
    const __half* __restrict__ khi, const __half* __restrict__ klo,
    const __half* __restrict__ vthi, const __half* __restrict__ vtlo,
    __half* __restrict__ ahi, __half* __restrict__ alo)
{
    extern __shared__ __half sh[];
    const u32 sb = smem_u32(sh);
    const int tid = threadIdx.x, w = tid >> 5, lane = tid & 31;
    const int bh = blockIdx.y, b = bh >> 4, hd = bh & 15;
    const int q0 = blockIdx.x * 128;
    const int wg = w >> 1, wn = w & 1;
    float* rmax = (float*)((char*)sh + ARED_B);   // [par][wn][128]
    float* lsum = rmax + 512;                     // [wn][128]
    float* ocmb = (float*)((char*)sh + AKV0 * 2); // [128][68]

    // Q loader
    {
        const int pl = tid >> 7, u = tid & 127, s = u & 7, r0 = u >> 3;
        const __half* qb = (pl ? qlo : qhi) + ((long)(b * LL + q0 + r0)) * DM + hd * 64 + s * 8;
        u32 d0 = sb + (u32)((pl * 9216 + r0 * 72 + s * 8) * 2);
#pragma unroll
        for (int it = 0; it < 8; it++) CPA16(d0 + it * (16 * 72 * 2), qb + (long)it * 16 * DM);
        CPC();
    }
    // KV loader state
    const int kpl = tid >> 6, ku = tid & 63, kls = ku & 7, klr0 = ku >> 3;
    const __half* kvb;
    long kvstep;
    if (kpl == 0)      { kvb = khi  + ((long)(b * LL + klr0)) * DM + hd * 64 + kls * 8; kvstep = (long)8 * DM; }
    else if (kpl == 1) { kvb = klo  + ((long)(b * LL + klr0)) * DM + hd * 64 + kls * 8; kvstep = (long)8 * DM; }
    else if (kpl == 2) { kvb = vthi + ((long)(bh * 64 + klr0)) * LL + kls * 8;          kvstep = (long)8 * LL; }
    else               { kvb = vtlo + ((long)(bh * 64 + klr0)) * LL + kls * 8;          kvstep = (long)8 * LL; }
    const long kvchunk = (kpl < 2) ? (long)64 * DM : 64;
    const u32 kdst0 = (u32)((kpl * 4608 + klr0 * 72 + kls * 8) * 2);

#pragma unroll
    for (int it = 0; it < 8; it++) CPA16(sb + AKV0 * 2 + kdst0 + it * (8 * 72 * 2), kvb + it * kvstep);
    CPC();

    float o[2][8][4];
#pragma unroll
    for (int mt = 0; mt < 2; mt++)
#pragma unroll
        for (int dt = 0; dt < 8; dt++)
#pragma unroll
            for (int r = 0; r < 4; r++) o[mt][dt][r] = 0.f;
    float mr[4] = { -1e30f, -1e30f, -1e30f, -1e30f }, lr[4] = { 0.f, 0.f, 0.f, 0.f };

    for (int c = 0; c < 32; c++) {
        CPW(0);
        __syncthreads();   // orders chunk c-1 reads before prefetch(c+1) writes
        if (c + 1 < 32) {
            u32 bo = (u32)(((c + 1) & 1) ? AKV1 * 2 : AKV0 * 2);
            const __half* src = kvb + (c + 1) * kvchunk;
#pragma unroll
            for (int it = 0; it < 8; it++) CPA16(sb + bo + kdst0 + it * (8 * 72 * 2), src + it * kvstep);
            CPC();
        }
        const u32 AKVB = (u32)((c & 1) ? AKV1 : AKV0);

        // ---- S = Q K^T (3 products), warp: rows wg*32..+32, keys wn*32..+32 ----
        float s[2][4][4];
#pragma unroll
        for (int mt = 0; mt < 2; mt++)
#pragma unroll
            for (int nt = 0; nt < 4; nt++)
#pragma unroll
                for (int r = 0; r < 4; r++) s[mt][nt][r] = 0.f;
#pragma unroll
        for (int ks = 0; ks < 4; ks++) {
            u32 qh_[2][4], ql_[2][4], kh_[4][2], kl_[4][2];
#pragma unroll
            for (int mt = 0; mt < 2; mt++) {
                u32 ra = sb + (u32)(((wg * 32 + mt * 16 + (lane & 15)) * 72 +
                                     ks * 16 + ((lane >> 4) & 1) * 8) * 2);
                ldsm4(qh_[mt][0], qh_[mt][1], qh_[mt][2], qh_[mt][3], ra);
                ldsm4(ql_[mt][0], ql_[mt][1], ql_[mt][2], ql_[mt][3], ra + 9216 * 2);
            }
#pragma unroll
            for (int nt = 0; nt < 4; nt++) {
                u32 rb = sb + (u32)((AKVB + (wn * 32 + nt * 8 + (lane & 7)) * 72 +
                                     ks * 16 + ((lane >> 3) & 1) * 8) * 2);
                ldsm2(kh_[nt][0], kh_[nt][1], rb);
                ldsm2(kl_[nt][0], kl_[nt][1], rb + 4608 * 2);
            }
#pragma unroll
            for (int mt = 0; mt < 2; mt++)
#pragma unroll
                for (int nt = 0; nt < 4; nt++) {
                    mma16(s[mt][nt], qh_[mt], kh_[nt]);
                    mma16(s[mt][nt], qh_[mt], kl_[nt]);
                    mma16(s[mt][nt], ql_[mt], kh_[nt]);
                }
        }

        // ---- online softmax (parity ping-pong max buffer; 1 extra sync) ----
        const int par = c & 1;
        float lmx[4], alpha[4];
#pragma unroll
        for (int mt = 0; mt < 2; mt++)
#pragma unroll
            for (int hh = 0; hh < 2; hh++) {
                int slot = mt * 2 + hh;
                float mx = -1e30f;
#pragma unroll
                for (int nt = 0; nt < 4; nt++) {
                    mx = fmaxf(mx, s[mt][nt][hh * 2]);
                    mx = fmaxf(mx, s[mt][nt][hh * 2 + 1]);
                }
                mx = fmaxf(mx, __shfl_xor_sync(0xffffffffu, mx, 1));
                mx = fmaxf(mx, __shfl_xor_sync(0xffffffffu, mx, 2));
                lmx[slot] = mx;
                if ((lane & 3) == 0)
                    rmax[par * 256 + wn * 128 + wg * 32 + mt * 16 + hh * 8 + (lane >> 2)] = mx;
            }
        __syncthreads();
#pragma unroll
        for (int mt = 0; mt < 2; mt++)
#pragma unroll
            for (int hh = 0; hh < 2; hh++) {
                int slot = mt * 2 + hh;
                int row = wg * 32 + mt * 16 + hh * 8 + (lane >> 2);
                float mn = fmaxf(mr[slot], fmaxf(lmx[slot], rmax[par * 256 + (1 - wn) * 128 + row]));
                alpha[slot] = ex2f(mr[slot] - mn);
                mr[slot] = mn;
            }
        // exponentiate in place
#pragma unroll
        for (int mt = 0; mt < 2; mt++)
#pragma unroll
            for (int nt = 0; nt < 4; nt++) {
                s[mt][nt][0] = ex2f(s[mt][nt][0] - mr[mt * 2]);
                s[mt][nt][1] = ex2f(s[mt][nt][1] - mr[mt * 2]);
                s[mt][nt][2] = ex2f(s[mt][nt][2] - mr[mt * 2 + 1]);
                s[mt][nt][3] = ex2f(s[mt][nt][3] - mr[mt * 2 + 1]);
            }
        // l update (local to key-half; combined at end — same alpha chain both halves)
#pragma unroll
        for (int mt = 0; mt < 2; mt++)
#pragma unroll
            for (int hh = 0; hh < 2; hh++) {
                int slot = mt * 2 + hh;
                float ssum = 0.f;
#pragma unroll
                for (int nt = 0; nt < 4; nt++) ssum += s[mt][nt][hh * 2] + s[mt][nt][hh * 2 + 1];
                ssum += __shfl_xor_sync(0xffffffffu, ssum, 1);
                ssum += __shfl_xor_sync(0xffffffffu, ssum, 2);
                lr[slot] = lr[slot] * alpha[slot] + ssum;
            }
        // O rescale
#pragma unroll
        for (int mt = 0; mt < 2; mt++)
#pragma unroll
            for (int dt = 0; dt < 8; dt++) {
                o[mt][dt][0] *= alpha[mt * 2];     o[mt][dt][1] *= alpha[mt * 2];
                o[mt][dt][2] *= alpha[mt * 2 + 1]; o[mt][dt][3] *= alpha[mt * 2 + 1];
            }
        // pack P a-frags directly from S c-frags (c-frag rows/cols == a-frag rows/k)
        u32 aP[2][2][4];
#pragma unroll
        for (int mt = 0; mt < 2; mt++)
#pragma unroll
            for (int ksl = 0; ksl < 2; ksl++) {
                aP[mt][ksl][0] = h2pk(s[mt][2 * ksl][0],     s[mt][2 * ksl][1]);
                aP[mt][ksl][1] = h2pk(s[mt][2 * ksl][2],     s[mt][2 * ksl][3]);
                aP[mt][ksl][2] = h2pk(s[mt][2 * ksl + 1][0], s[mt][2 * ksl + 1][1]);
                aP[mt][ksl][3] = h2pk(s[mt][2 * ksl + 1][2], s[mt][2 * ksl + 1][3]);
            }
        // ---- O += P V (2 products: V hi + V lo), k-slice = warp's 32 keys ----
#pragma unroll
        for (int ksl = 0; ksl < 2; ksl++) {
            u32 vh_[8][2], vl_[8][2];
#pragma unroll
            for (int dt = 0; dt < 8; dt++) {
                u32 rb = sb + (u32)((AKVB + 9216 + (dt * 8 + (lane & 7)) * 72 +
                                     wn * 32 + ksl * 16 + ((lane >> 3) & 1) * 8) * 2);
                ldsm2(vh_[dt][0], vh_[dt][1], rb);
                ldsm2(vl_[dt][0], vl_[dt][1], rb + 4608 * 2);
            }
#pragma unroll
            for (int mt = 0; mt < 2; mt++)
#pragma unroll
                for (int dt = 0; dt < 8; dt++) {
                    mma16(o[mt][dt], aP[mt][ksl], vh_[dt]);
                    mma16(o[mt][dt], aP[mt][ksl], vl_[dt]);
                }
        }
    }

    // ---- final combine across key-halves ----
    __syncthreads();   // all PV done; KV0 smem free for O-combine
#pragma unroll
    for (int mt = 0; mt < 2; mt++)
#pragma unroll
        for (int hh = 0; hh < 2; hh++) {
            int slot = mt * 2 + hh;
            if ((lane & 3) == 0)
                lsum[wn * 128 + wg * 32 + mt * 16 + hh * 8 + (lane >> 2)] = lr[slot];
        }
    if (wn == 1) {
#pragma unroll
        for (int mt = 0; mt < 2; mt++)
#pragma unroll
            for (int dt = 0; dt < 8; dt++) {
                int r = wg * 32 + mt * 16 + (lane >> 2);
                int cc = dt * 8 + (lane & 3) * 2;
                *(float2*)&ocmb[r * 68 + cc]       = make_float2(o[mt][dt][0], o[mt][dt][1]);
                *(float2*)&ocmb[(r + 8) * 68 + cc] = make_float2(o[mt][dt][2], o[mt][dt][3]);
            }
    }
    __syncthreads();
    if (wn == 0) {
        float inv[4];
#pragma unroll
        for (int mt = 0; mt < 2; mt++)
#pragma unroll
            for (int hh = 0; hh < 2; hh++) {
                int slot = mt * 2 + hh;
                int row = wg * 32 + mt * 16 + hh * 8 + (lane >> 2);
                inv[slot] = 1.0f / (lr[slot] + lsum[128 + row]);
            }
#pragma unroll
        for (int mt = 0; mt < 2; mt++)
#pragma unroll
            for (int dt = 0; dt < 8; dt++) {
                int r = wg * 32 + mt * 16 + (lane >> 2);
                int cc = dt * 8 + (lane & 3) * 2;
                float2 p0 = *(float2*)&ocmb[r * 68 + cc];
                float2 p1 = *(float2*)&ocmb[(r + 8) * 68 + cc];
                float v0 = (o[mt][dt][0] + p0.x) * inv[mt * 2];
                float v1 = (o[mt][dt][1] + p0.y) * inv[mt * 2];
                float v2 = (o[mt][dt][2] + p1.x) * inv[mt * 2 + 1];
                float v3 = (o[mt][dt][3] + p1.y) * inv[mt * 2 + 1];
                __half h0 = __float2half_rn(v0), h1 = __float2half_rn(v1);
                __half h2v = __float2half_rn(v2), h3 = __float2half_rn(v3);
                __half l0 = __float2half_rn(v0 - __half2float(h0));
                __half l1 = __float2half_rn(v1 - __half2float(h1));
                __half l2 = __float2half_rn(v2 - __half2float(h2v));
                __half l3 = __float2half_rn(v3 - __half2float(h3));
                long off0 = ((long)(b * LL + q0 + r)) * DM + hd * 64 + cc;
                long off1 = ((long)(b * LL + q0 + r + 8)) * DM + hd * 64 + cc;
                *(__half2*)(ahi + off0) = __halves2half2(h0, h1);
                *(__half2*)(alo + off0) = __halves2half2(l0, l1);
                *(__half2*)(ahi + off1) = __halves2half2(h2v, h3);
                *(__half2*)(alo + off1) = __halves2half2(l2, l3);
            }
    }
}

// =====================================================================
// Final RMS norm: out = y * g_out * 32 / max(||y||, eps)
// =====================================================================
__global__ __launch_bounds__(256) void final_norm_kernel(
    const float* __restrict__ in, const float* __restrict__ g, float* __restrict__ outp)
{
    long row = blockIdx.x;
    const float* p = in + row * (long)DM;
    int c = threadIdx.x * 4;
    float4 v = *(const float4*)(p + c);
    float s = v.x * v.x + v.y * v.y + v.z * v.z + v.w * v.w;
#pragma unroll
    for (int m = 16; m; m >>= 1) s += __shfl_xor_sync(0xffffffffu, s, m);
    __shared__ float ws[8];
    __shared__ float fac;
    int w = threadIdx.x >> 5;
    if ((threadIdx.x & 31) == 0) ws[w] = s;
    __syncthreads();
    if (threadIdx.x == 0) {
        float a = 0.f;
#pragma unroll
        for (int i = 0; i < 8; i++) a += ws[i];
        fac = 32.0f / fmaxf(sqrtf(a), 1e-12f);
    }
    __syncthreads();
    float f = fac;
    float4 g4 = *(const float4*)(g + c);
    float4 o = make_float4(v.x * f * g4.x, v.y * f * g4.y, v.z * f * g4.z, v.w * f * g4.w);
    *(float4*)(outp + row * (long)DM + c) = o;
}

// =====================================================================
// launch
// =====================================================================
extern "C" void kernel_launch(void* const* d_in, const int* in_sizes, int n_in,
                              void* d_out, int out_size)
{
    const float* x    = (const float*)d_in[0];
    const float* Wqkv = (const float*)d_in[1];
    const float* bqkv = (const float*)d_in[2];
    const float* Wout = (const float*)d_in[3];
    const float* bout = (const float*)d_in[4];
    const float* gq   = (const float*)d_in[5];
    const float* gk   = (const float*)d_in[6];
    const float* gout = (const float*)d_in[7];
    float* out = (float*)d_out;

    float *qkv, *prj;
    __half *xhi, *xlo, *whi, *wlo, *wohi, *wolo;
    __half *Qhi, *Qlo, *Khi, *Klo, *Ahi, *Alo, *Vthi, *Vtlo;
    cudaGetSymbolAddress((void**)&qkv, g_qkv);
    cudaGetSymbolAddress((void**)&prj, g_prj);
    cudaGetSymbolAddress((void**)&xhi, g_xhi);   cudaGetSymbolAddress((void**)&xlo, g_xlo);
    cudaGetSymbolAddress((void**)&whi, g_whi);   cudaGetSymbolAddress((void**)&wlo, g_wlo);
    cudaGetSymbolAddress((void**)&wohi, g_wohi); cudaGetSymbolAddress((void**)&wolo, g_wolo);
    cudaGetSymbolAddress((void**)&Qhi, g_qhi);   cudaGetSymbolAddress((void**)&Qlo, g_qlo);
    cudaGetSymbolAddress((void**)&Khi, g_khi);   cudaGetSymbolAddress((void**)&Klo, g_klo);
    cudaGetSymbolAddress((void**)&Ahi, g_ahi);   cudaGetSymbolAddress((void**)&Alo, g_alo);
    cudaGetSymbolAddress((void**)&Vthi, g_vthi); cudaGetSymbolAddress((void**)&Vtlo, g_vtlo);

    cudaFuncSetAttribute(gemm_mma, cudaFuncAttributeMaxDynamicSharedMemorySize, GM_SMEM);
    cudaFuncSetAttribute(attn_mma, cudaFuncAttributeMaxDynamicSharedMemorySize, AT_SMEM);

    // 0) fp32 -> fp16 hi/lo splits
    long n_x = (long)MR * DM / 4, n_w = (long)N3 * DM / 4, n_wo = (long)DM * DM / 4;
    conv_hilo<<<(unsigned)((n_x  + 255) / 256), 256>>>(x,    xhi,  xlo,  n_x);
    conv_hilo<<<(unsigned)((n_w  + 255) / 256), 256>>>(Wqkv, whi,  wlo,  n_w);
    conv_hilo<<<(unsigned)((n_wo + 255) / 256), 256>>>(Wout, wohi, wolo, n_wo);

    // 1) QKV projection
    gemm_mma<<<dim3(N3 / 128, MR / 128), 256, GM_SMEM>>>(xhi, xlo, whi, wlo, bqkv, qkv, N3, DM);

    // 2) q/k norm -> fp16 hi/lo ; V -> transposed fp16 hi/lo
    qk_norm<<<MR, 256>>>(qkv, gq, gk, Qhi, Qlo, Khi, Klo);
    v_trans<<<dim3(LL / 128, BB * NH), 256>>>(qkv, Vthi, Vtlo);

    // 3) attention (register-P FA2)
    attn_mma<<<dim3(LL / 128, BB * NH), 256, AT_SMEM>>>(Qhi, Qlo, Khi, Klo, Vthi, Vtlo, Ahi, Alo);

    // 4) output projection (3 products — keeps error margin)
    gemm_mma<<<dim3(DM / 128, MR / 128), 256, GM_SMEM>>>(Ahi, Alo, wohi, wolo, bout, prj, DM, DM);

    // 5) final RMS norm -> d_out
    final_norm_kernel<<<MR, 256>>>(prj, gout, out);
}

// round 13
// speedup vs baseline: 1.5320x; 1.5320x over previous
#include <cuda_runtime.h>
#include <cuda_fp16.h>

typedef unsigned int u32;
typedef unsigned long long u64;

// ---------------- problem constants ----------------
#define BB 4
#define LL 2048
#define DM 1024
#define NH 16
#define MR 8192
#define N3 3072

// ---------------- scratch (device globals; allocation is forbidden) ----------------
__device__ float g_qkv[(size_t)MR * N3];
__device__ float g_prj[(size_t)MR * DM];
__device__ __half g_xhi[(size_t)MR * DM],  g_xlo[(size_t)MR * DM];
__device__ __half g_whi[(size_t)N3 * DM],  g_wlo[(size_t)N3 * DM];
__device__ __half g_wohi[(size_t)DM * DM], g_wolo[(size_t)DM * DM];
__device__ __half g_qhi[(size_t)MR * DM],  g_qlo[(size_t)MR * DM];
__device__ __half g_khi[(size_t)MR * DM],  g_klo[(size_t)MR * DM];
__device__ __half g_ahi[(size_t)MR * DM],  g_alo[(size_t)MR * DM];
__device__ __half g_vthi[(size_t)BB * NH * 64 * LL], g_vtlo[(size_t)BB * NH * 64 * LL];

// ---------------- portable PTX helpers ----------------
__device__ __forceinline__ u32 smem_u32(const void* p) {
    u32 a;
    asm("{ .reg .u64 t; cvta.to.shared.u64 t, %1; cvt.u32.u64 %0, t; }" : "=r"(a) : "l"(p));
    return a;
}
__device__ __forceinline__ void ldsm4(u32& r0, u32& r1, u32& r2, u32& r3, u32 a) {
    asm volatile("ldmatrix.sync.aligned.m8n8.x4.shared.b16 {%0,%1,%2,%3},[%4];"
                 : "=r"(r0), "=r"(r1), "=r"(r2), "=r"(r3) : "r"(a));
}
__device__ __forceinline__ void ldsm2(u32& r0, u32& r1, u32 a) {
    asm volatile("ldmatrix.sync.aligned.m8n8.x2.shared.b16 {%0,%1},[%2];"
                 : "=r"(r0), "=r"(r1) : "r"(a));
}
__device__ __forceinline__ void mma16(float* c, const u32* a, const u32* b) {
    asm volatile("mma.sync.aligned.m16n8k16.row.col.f32.f16.f16.f32 "
                 "{%0,%1,%2,%3},{%4,%5,%6,%7},{%8,%9},{%0,%1,%2,%3};"
                 : "+f"(c[0]), "+f"(c[1]), "+f"(c[2]), "+f"(c[3])
                 : "r"(a[0]), "r"(a[1]), "r"(a[2]), "r"(a[3]), "r"(b[0]), "r"(b[1]));
}
__device__ __forceinline__ float ex2f(float x) {
    float y; asm("ex2.approx.f32 %0,%1;" : "=f"(y) : "f"(x)); return y;
}
__device__ __forceinline__ u32 h2pk(float a, float b) {
    __half2 t = __float22half2_rn(make_float2(a, b));
    return *(u32*)&t;
}
#define CPA16(d, s) asm volatile("cp.async.cg.shared.global [%0],[%1],16;" :: "r"(d), "l"(s) : "memory")
#define CPC()       asm volatile("cp.async.commit_group;" ::: "memory")
#define CPW(n)      asm volatile("cp.async.wait_group %0;" :: "n"(n) : "memory")

// =====================================================================
// fp32 -> fp16 hi/lo planar split
// =====================================================================
__global__ __launch_bounds__(256) void conv_hilo(
    const float* __restrict__ src, __half* __restrict__ hi,
    __half* __restrict__ lo, long n4)
{
    long i = (long)blockIdx.x * 256 + threadIdx.x;
    if (i >= n4) return;
    float4 v = ((const float4*)src)[i];
    float f[4] = { v.x, v.y, v.z, v.w };
    __half h[4], l[4];
#pragma unroll
    for (int e = 0; e < 4; e++) {
        h[e] = __float2half_rn(f[e]);
        l[e] = __float2half_rn(f[e] - __half2float(h[e]));
    }
    ((uint2*)hi)[i] = *(uint2*)h;
    ((uint2*)lo)[i] = *(uint2*)l;
}

// =====================================================================
// HMMA TN GEMM, fp16 hi/lo (3 products): C = A B^T + bias, fp32 out.
// 128x128 tile, 256 thr, K-chunk 32, double-buffered, 2 CTAs/SM.
// Prefetch-EARLY loop (loads in flight during CPW wait) made race-safe
// by the bottom __syncthreads(): all reads of buf[(c-1)&1] complete
// before any warp enters iteration c and writes buf[(c+1)&1].
// =====================================================================
#define GSTR 40
#define GPL  5120
#define GBUF 20480
#define GM_SMEM (2 * GBUF * 2)

__global__ __launch_bounds__(256, 2) void gemm_mma(
    const __half* __restrict__ Ahi, const __half* __restrict__ Alo,
    const __half* __restrict__ Bhi, const __half* __restrict__ Blo,
    const float* __restrict__ bias, float* __restrict__ C, int N, int K)
{
    extern __shared__ __half sh[];
    const u32 sb = smem_u32(sh);
    const int tid = threadIdx.x, w = tid >> 5, lane = tid & 31;
    const int bm = blockIdx.y * 128, bn = blockIdx.x * 128;
    const int wm = (w >> 2) * 64, wn = (w & 3) * 32;

    float acc[4][4][4];
#pragma unroll
    for (int mt = 0; mt < 4; mt++)
#pragma unroll
        for (int nt = 0; nt < 4; nt++)
#pragma unroll
            for (int r = 0; r < 4; r++) acc[mt][nt][r] = 0.f;

    const int pl = tid >> 6, lu = tid & 63, ls = lu & 3, lr0 = lu >> 2;
    const __half* lbase = ((pl == 0) ? Ahi : (pl == 1) ? Alo : (pl == 2) ? Bhi : Blo)
                          + (long)((pl < 2 ? bm : bn) + lr0) * K + ls * 8;
    const u32 ldst0 = (u32)((pl * GPL + lr0 * GSTR + ls * 8) * 2);
    const long lrowstride = (long)16 * K;

    const int nch = K / 32;
#pragma unroll
    for (int it = 0; it < 8; it++) CPA16(sb + ldst0 + it * (16 * GSTR * 2), lbase + it * lrowstride);
    CPC();

    for (int c = 0; c < nch; c++) {
        if (c + 1 < nch) {
            u32 bo = (u32)(((c + 1) & 1) * GBUF * 2);
            const __half* src = lbase + (c + 1) * 32;
#pragma unroll
            for (int it = 0; it < 8; it++) CPA16(sb + bo + ldst0 + it * (16 * GSTR * 2), src + it * lrowstride);
            CPC();
            CPW(1);
        } else {
            CPW(0);
        }
        __syncthreads();
        u32 base = sb + (u32)((c & 1) * GBUF * 2);
#pragma unroll
        for (int ks = 0; ks < 2; ks++) {
            u32 ah[4][4], al[4][4], bh[4][2], bl[4][2];
#pragma unroll
            for (int mt = 0; mt < 4; mt++) {
                u32 ra = base + (u32)(((wm + mt * 16 + (lane & 15)) * GSTR +
                                       ks * 16 + ((lane >> 4) & 1) * 8) * 2);
                ldsm4(ah[mt][0], ah[mt][1], ah[mt][2], ah[mt][3], ra);
                ldsm4(al[mt][0], al[mt][1], al[mt][2], al[mt][3], ra + GPL * 2);
            }
#pragma unroll
            for (int nt = 0; nt < 4; nt++) {
                u32 rb = base + (u32)((2 * GPL + (wn + nt * 8 + (lane & 7)) * GSTR +
                                       ks * 16 + ((lane >> 3) & 1) * 8) * 2);
                ldsm2(bh[nt][0], bh[nt][1], rb);
                ldsm2(bl[nt][0], bl[nt][1], rb + GPL * 2);
            }
#pragma unroll
            for (int mt = 0; mt < 4; mt++)
#pragma unroll
                for (int nt = 0; nt < 4; nt++) {
                    mma16(acc[mt][nt], ah[mt], bh[nt]);
                    mma16(acc[mt][nt], ah[mt], bl[nt]);
                    mma16(acc[mt][nt], al[mt], bh[nt]);
                }
        }
        __syncthreads();   // race guard: buf[(c-1)&1] reads done before prefetch writes in c+1
    }
    // epilogue
#pragma unroll
    for (int mt = 0; mt < 4; mt++) {
        int r0 = bm + wm + mt * 16 + (lane >> 2);
#pragma unroll
        for (int nt = 0; nt < 4; nt++) {
            int cb = bn + wn + nt * 8 + 2 * (lane & 3);
            float2 bv = *(const float2*)(bias + cb);
            float2 o0 = make_float2(acc[mt][nt][0] + bv.x, acc[mt][nt][1] + bv.y);
            float2 o1 = make_float2(acc[mt][nt][2] + bv.x, acc[mt][nt][3] + bv.y);
            *(float2*)(C + (long)r0 * N + cb) = o0;
            *(float2*)(C + (long)(r0 + 8) * N + cb) = o1;
        }
    }
}

// =====================================================================
// q/k RMS norm -> fp16 hi/lo. q folds g*4*log2(e)/||q||, k folds g*32/||k||
// =====================================================================
__global__ __launch_bounds__(256) void qk_norm(
    const float* __restrict__ qkv,
    const float* __restrict__ gq, const float* __restrict__ gk,
    __half* __restrict__ qhi, __half* __restrict__ qlo,
    __half* __restrict__ khi, __half* __restrict__ klo)
{
    long row = blockIdx.x;
    const float* p = qkv + row * (long)N3;
    int c = threadIdx.x * 4;
    float4 q4 = *(const float4*)(p + c);
    float4 k4 = *(const float4*)(p + DM + c);
    float sq = q4.x * q4.x + q4.y * q4.y + q4.z * q4.z + q4.w * q4.w;
    float sk = k4.x * k4.x + k4.y * k4.y + k4.z * k4.z + k4.w * k4.w;
#pragma unroll
    for (int m = 16; m; m >>= 1) {
        sq += __shfl_xor_sync(0xffffffffu, sq, m);
        sk += __shfl_xor_sync(0xffffffffu, sk, m);
    }
    __shared__ float2 ws[8];
    __shared__ float2 fac;
    int w = threadIdx.x >> 5;
    if ((threadIdx.x & 31) == 0) ws[w] = make_float2(sq, sk);
    __syncthreads();
    if (threadIdx.x == 0) {
        float a = 0.f, bsum = 0.f;
#pragma unroll
        for (int i = 0; i < 8; i++) { a += ws[i].x; bsum += ws[i].y; }
        fac = make_float2(5.770780163555851f / fmaxf(sqrtf(a), 1e-12f),   // 4*log2(e)
                          32.0f / fmaxf(sqrtf(bsum), 1e-12f));
    }
    __syncthreads();
    float fq = fac.x, fk = fac.y;
    float4 gq4 = *(const float4*)(gq + c);
    float4 gk4 = *(const float4*)(gk + c);
    float qs[4] = { q4.x * fq * gq4.x, q4.y * fq * gq4.y, q4.z * fq * gq4.z, q4.w * fq * gq4.w };
    float ks[4] = { k4.x * fk * gk4.x, k4.y * fk * gk4.y, k4.z * fk * gk4.z, k4.w * fk * gk4.w };
    __half qh[4], ql[4], kh[4], kl[4];
#pragma unroll
    for (int e = 0; e < 4; e++) {
        qh[e] = __float2half_rn(qs[e]); ql[e] = __float2half_rn(qs[e] - __half2float(qh[e]));
        kh[e] = __float2half_rn(ks[e]); kl[e] = __float2half_rn(ks[e] - __half2float(kh[e]));
    }
    long o = row * (long)DM + c;
    *(uint2*)(qhi + o) = *(uint2*)qh;  *(uint2*)(qlo + o) = *(uint2*)ql;
    *(uint2*)(khi + o) = *(uint2*)kh;  *(uint2*)(klo + o) = *(uint2*)kl;
}

// =====================================================================
// V transpose: qkv v-part (b,l,h*64+d) fp32 -> fp16 hi/lo [(bh*64+d)][l]
// =====================================================================
#define VT_STR 136
__global__ __launch_bounds__(256) void v_trans(
    const float* __restrict__ qkv, __half* __restrict__ vthi, __half* __restrict__ vtlo)
{
    __shared__ __half shi[64 * VT_STR], slo[64 * VT_STR];
    int bh = blockIdx.y, b = bh >> 4, h = bh & 15;
    int l0 = blockIdx.x * 128;
    int tid = threadIdx.x;
#pragma unroll
    for (int it = 0; it < 8; it++) {
        int idx = it * 256 + tid;
        int l = idx >> 4, d4 = (idx & 15) * 4;
        float4 v = *(const float4*)(qkv + ((long)(b * LL + l0 + l)) * N3 + 2 * DM + h * 64 + d4);
        float f[4] = { v.x, v.y, v.z, v.w };
#pragma unroll
        for (int e = 0; e < 4; e++) {
            __half hv = __float2half_rn(f[e]);
            __half lv = __float2half_rn(f[e] - __half2float(hv));
            shi[(d4 + e) * VT_STR + l] = hv;
            slo[(d4 + e) * VT_STR + l] = lv;
        }
    }
    __syncthreads();
#pragma unroll
    for (int it = 0; it < 8; it++) {
        int i = it * 256 + tid;
        int pl = i >> 10, j = i & 1023;
        int d = j >> 4, s = j & 15;
        uint4 v = *(uint4*)&((pl ? slo : shi)[d * VT_STR + s * 8]);
        *(uint4*)((pl ? vtlo : vthi) + ((long)bh * 64 + d) * LL + l0 + s * 8) = v;
    }
}

// =====================================================================
// HMMA flash attention, register-resident P (FA2 style) — validated R12.
// Block = (128-q tile, bh). 8 warps = 4 row-groups x 2 key-halves.
// S: 3 hi/lo products. PV: P fp16 (registers) x V hi/lo = 2 products.
// smem (halves): QHI 0, QLO 9216, KV0 18432, KV1 36864
//   (per buf: Khi +0, Klo +4608, Vhi +9216, Vlo +13824)
// floats: rmax[2][2][128] @ byte 110592, lsum[2][128] after it.
// O-combine region (floats, stride 68) reuses KV0 space @ byte 36864.
// =====================================================================
#define AKV0 18432
#define AKV1 36864
#define ARED_B 110592
#define AT_SMEM (110592 + 3072)

__global__ __launch_bounds__(256) void attn_mma(
    const __half* __restrict__ qhi, const __half* __restrict__ qlo,
    const __half* __restrict__ khi, const __half* __restrict__ klo,
    const __half* __restrict__ vthi, const __half* __restrict__ vtlo,
    __half* __restrict__ ahi, __half* __restrict__ alo)
{
    extern __shared__ __half sh[];
    const u32 sb = smem_u32(sh);
    const int tid = threadIdx.x, w = tid >> 5, lane = tid & 31;
    const int bh = blockIdx.y, b = bh >> 4, hd = bh & 15;
    const int q0 = blockIdx.x * 128;
    const int wg = w >> 1, wn = w & 1;
    float* rmax = (float*)((char*)sh + ARED_B);   // [par][wn][128]
    float* lsum = rmax + 512;                     // [wn][128]
    float* ocmb = (float*)((char*)sh + AKV0 * 2); // [128][68]

    // Q loader
    {
        const int pl = tid >> 7, u = tid & 127, s = u & 7, r0 = u >> 3;
        const __half* qb = (pl ? qlo : qhi) + ((long)(b * LL + q0 + r0)) * DM + hd * 64 + s * 8;
        u32 d0 = sb + (u32)((pl * 9216 + r0 * 72 + s * 8) * 2);
#pragma unroll
        for (int it = 0; it < 8; it++) CPA16(d0 + it * (16 * 72 * 2), qb + (long)it * 16 * DM);
        CPC();
    }
    // KV loader state
    const int kpl = tid >> 6, ku = tid & 63, kls = ku & 7, klr0 = ku >> 3;
    const __half* kvb;
    long kvstep;
    if (kpl == 0)      { kvb = khi  + ((long)(b * LL + klr0)) * DM + hd * 64 + kls * 8; kvstep = (long)8 * DM; }
    else if (kpl == 1) { kvb = klo  + ((long)(b * LL + klr0)) * DM + hd * 64 + kls * 8; kvstep = (long)8 * DM; }
    else if (kpl == 2) { kvb = vthi + ((long)(bh * 64 + klr0)) * LL + kls * 8;          kvstep = (long)8 * LL; }
    else               { kvb = vtlo + ((long)(bh * 64 + klr0)) * LL + kls * 8;          kvstep = (long)8 * LL; }
    const long kvchunk = (kpl < 2) ? (long)64 * DM : 64;
    const u32 kdst0 = (u32)((kpl * 4608 + klr0 * 72 + kls * 8) * 2);

#pragma unroll
    for (int it = 0; it < 8; it++) CPA16(sb + AKV0 * 2 + kdst0 + it * (8 * 72 * 2), kvb + it * kvstep);
    CPC();

    float o[2][8][4];
#pragma unroll
    for (int mt = 0; mt < 2; mt++)
#pragma unroll
        for (int dt = 0; dt < 8; dt++)
#pragma unroll
            for (int r = 0; r < 4; r++) o[mt][dt][r] = 0.f;
    float mr[4] = { -1e30f, -1e30f, -1e30f, -1e30f }, lr[4] = { 0.f, 0.f, 0.f, 0.f };

    for (int c = 0; c < 32; c++) {
        CPW(0);
        __syncthreads();   // orders chunk c-1 reads before prefetch(c+1) writes
        if (c + 1 < 32) {
            u32 bo = (u32)(((c + 1) & 1) ? AKV1 * 2 : AKV0 * 2);
            const __half* src = kvb + (c + 1) * kvchunk;
#pragma unroll
            for (int it = 0; it < 8; it++) CPA16(sb + bo + kdst0 + it * (8 * 72 * 2), src + it * kvstep);
            CPC();
        }
        const u32 AKVB = (u32)((c & 1) ? AKV1 : AKV0);

        // ---- S = Q K^T (3 products), warp: rows wg*32..+32, keys wn*32..+32 ----
        float s[2][4][4];
#pragma unroll
        for (int mt = 0; mt < 2; mt++)
#pragma unroll
            for (int nt = 0; nt < 4; nt++)
#pragma unroll
                for (int r = 0; r < 4; r++) s[mt][nt][r] = 0.f;
#pragma unroll
        for (int ks = 0; ks < 4; ks++) {
            u32 qh_[2][4], ql_[2][4], kh_[4][2], kl_[4][2];
#pragma unroll
            for (int mt = 0; mt < 2; mt++) {
                u32 ra = sb + (u32)(((wg * 32 + mt * 16 + (lane & 15)) * 72 +
                                     ks * 16 + ((lane >> 4) & 1) * 8) * 2);
                ldsm4(qh_[mt][0], qh_[mt][1], qh_[mt][2], qh_[mt][3], ra);
                ldsm4(ql_[mt][0], ql_[mt][1], ql_[mt][2], ql_[mt][3], ra + 9216 * 2);
            }
#pragma unroll
            for (int nt = 0; nt < 4; nt++) {
                u32 rb = sb + (u32)((AKVB + (wn * 32 + nt * 8 + (lane & 7)) * 72 +
                                     ks * 16 + ((lane >> 3) & 1) * 8) * 2);
                ldsm2(kh_[nt][0], kh_[nt][1], rb);
                ldsm2(kl_[nt][0], kl_[nt][1], rb + 4608 * 2);
            }
#pragma unroll
            for (int mt = 0; mt < 2; mt++)
#pragma unroll
                for (int nt = 0; nt < 4; nt++) {
                    mma16(s[mt][nt], qh_[mt], kh_[nt]);
                    mma16(s[mt][nt], qh_[mt], kl_[nt]);
                    mma16(s[mt][nt], ql_[mt], kh_[nt]);
                }
        }

        // ---- online softmax (parity ping-pong max buffer; 1 extra sync) ----
        const int par = c & 1;
        float lmx[4], alpha[4];
#pragma unroll
        for (int mt = 0; mt < 2; mt++)
#pragma unroll
            for (int hh = 0; hh < 2; hh++) {
                int slot = mt * 2 + hh;
                float mx = -1e30f;
#pragma unroll
                for (int nt = 0; nt < 4; nt++) {
                    mx = fmaxf(mx, s[mt][nt][hh * 2]);
                    mx = fmaxf(mx, s[mt][nt][hh * 2 + 1]);
                }
                mx = fmaxf(mx, __shfl_xor_sync(0xffffffffu, mx, 1));
                mx = fmaxf(mx, __shfl_xor_sync(0xffffffffu, mx, 2));
                lmx[slot] = mx;
                if ((lane & 3) == 0)
                    rmax[par * 256 + wn * 128 + wg * 32 + mt * 16 + hh * 8 + (lane >> 2)] = mx;
            }
        __syncthreads();
#pragma unroll
        for (int mt = 0; mt < 2; mt++)
#pragma unroll
            for (int hh = 0; hh < 2; hh++) {
                int slot = mt * 2 + hh;
                int row = wg * 32 + mt * 16 + hh * 8 + (lane >> 2);
                float mn = fmaxf(mr[slot], fmaxf(lmx[slot], rmax[par * 256 + (1 - wn) * 128 + row]));
                alpha[slot] = ex2f(mr[slot] - mn);
                mr[slot] = mn;
            }
        // exponentiate in place
#pragma unroll
        for (int mt = 0; mt < 2; mt++)
#pragma unroll
            for (int nt = 0; nt < 4; nt++) {
                s[mt][nt][0] = ex2f(s[mt][nt][0] - mr[mt * 2]);
                s[mt][nt][1] = ex2f(s[mt][nt][1] - mr[mt * 2]);
                s[mt][nt][2] = ex2f(s[mt][nt][2] - mr[mt * 2 + 1]);
                s[mt][nt][3] = ex2f(s[mt][nt][3] - mr[mt * 2 + 1]);
            }
        // l update (local to key-half; combined at end)
#pragma unroll
        for (int mt = 0; mt < 2; mt++)
#pragma unroll
            for (int hh = 0; hh < 2; hh++) {
                int slot = mt * 2 + hh;
                float ssum = 0.f;
#pragma unroll
                for (int nt = 0; nt < 4; nt++) ssum += s[mt][nt][hh * 2] + s[mt][nt][hh * 2 + 1];
                ssum += __shfl_xor_sync(0xffffffffu, ssum, 1);
                ssum += __shfl_xor_sync(0xffffffffu, ssum, 2);
                lr[slot] = lr[slot] * alpha[slot] + ssum;
            }
        // O rescale
#pragma unroll
        for (int mt = 0; mt < 2; mt++)
#pragma unroll
            for (int dt = 0; dt < 8; dt++) {
                o[mt][dt][0] *= alpha[mt * 2];     o[mt][dt][1] *= alpha[mt * 2];
                o[mt][dt][2] *= alpha[mt * 2 + 1]; o[mt][dt][3] *= alpha[mt * 2 + 1];
            }
        // pack P a-frags directly from S c-frags
        u32 aP[2][2][4];
#pragma unroll
        for (int mt = 0; mt < 2; mt++)
#pragma unroll
            for (int ksl = 0; ksl < 2; ksl++) {
                aP[mt][ksl][0] = h2pk(s[mt][2 * ksl][0],     s[mt][2 * ksl][1]);
                aP[mt][ksl][1] = h2pk(s[mt][2 * ksl][2],     s[mt][2 * ksl][3]);
                aP[mt][ksl][2] = h2pk(s[mt][2 * ksl + 1][0], s[mt][2 * ksl + 1][1]);
                aP[mt][ksl][3] = h2pk(s[mt][2 * ksl + 1][2], s[mt][2 * ksl + 1][3]);
            }
        // ---- O += P V (2 products: V hi + V lo), k-slice = warp's 32 keys ----
#pragma unroll
        for (int ksl = 0; ksl < 2; ksl++) {
            u32 vh_[8][2], vl_[8][2];
#pragma unroll
            for (int dt = 0; dt < 8; dt++) {
                u32 rb = sb + (u32)((AKVB + 9216 + (dt * 8 + (lane & 7)) * 72 +
                                     wn * 32 + ksl * 16 + ((lane >> 3) & 1) * 8) * 2);
                ldsm2(vh_[dt][0], vh_[dt][1], rb);
                ldsm2(vl_[dt][0], vl_[dt][1], rb + 4608 * 2);
            }
#pragma unroll
            for (int mt = 0; mt < 2; mt++)
#pragma unroll
                for (int dt = 0; dt < 8; dt++) {
                    mma16(o[mt][dt], aP[mt][ksl], vh_[dt]);
                    mma16(o[mt][dt], aP[mt][ksl], vl_[dt]);
                }
        }
    }

    // ---- final combine across key-halves ----
    __syncthreads();   // all PV done; KV0 smem free for O-combine
#pragma unroll
    for (int mt = 0; mt < 2; mt++)
#pragma unroll
        for (int hh = 0; hh < 2; hh++) {
            int slot = mt * 2 + hh;
            if ((lane & 3) == 0)
                lsum[wn * 128 + wg * 32 + mt * 16 + hh * 8 + (lane >> 2)] = lr[slot];
        }
    if (wn == 1) {
#pragma unroll
        for (int mt = 0; mt < 2; mt++)
#pragma unroll
            for (int dt = 0; dt < 8; dt++) {
                int r = wg * 32 + mt * 16 + (lane >> 2);
                int cc = dt * 8 + (lane & 3) * 2;
                *(float2*)&ocmb[r * 68 + cc]       = make_float2(o[mt][dt][0], o[mt][dt][1]);
                *(float2*)&ocmb[(r + 8) * 68 + cc] = make_float2(o[mt][dt][2], o[mt][dt][3]);
            }
    }
    __syncthreads();
    if (wn == 0) {
        float inv[4];
#pragma unroll
        for (int mt = 0; mt < 2; mt++)
#pragma unroll
            for (int hh = 0; hh < 2; hh++) {
                int slot = mt * 2 + hh;
                int row = wg * 32 + mt * 16 + hh * 8 + (lane >> 2);
                inv[slot] = 1.0f / (lr[slot] + lsum[128 + row]);
            }
#pragma unroll
        for (int mt = 0; mt < 2; mt++)
#pragma unroll
            for (int dt = 0; dt < 8; dt++) {
                int r = wg * 32 + mt * 16 + (lane >> 2);
                int cc = dt * 8 + (lane & 3) * 2;
                float2 p0 = *(float2*)&ocmb[r * 68 + cc];
                float2 p1 = *(float2*)&ocmb[(r + 8) * 68 + cc];
                float v0 = (o[mt][dt][0] + p0.x) * inv[mt * 2];
                float v1 = (o[mt][dt][1] + p0.y) * inv[mt * 2];
                float v2 = (o[mt][dt][2] + p1.x) * inv[mt * 2 + 1];
                float v3 = (o[mt][dt][3] + p1.y) * inv[mt * 2 + 1];
                __half h0 = __float2half_rn(v0), h1 = __float2half_rn(v1);
                __half h2v = __float2half_rn(v2), h3 = __float2half_rn(v3);
                __half l0 = __float2half_rn(v0 - __half2float(h0));
                __half l1 = __float2half_rn(v1 - __half2float(h1));
                __half l2 = __float2half_rn(v2 - __half2float(h2v));
                __half l3 = __float2half_rn(v3 - __half2float(h3));
                long off0 = ((long)(b * LL + q0 + r)) * DM + hd * 64 + cc;
                long off1 = ((long)(b * LL + q0 + r + 8)) * DM + hd * 64 + cc;
                *(__half2*)(ahi + off0) = __halves2half2(h0, h1);
                *(__half2*)(alo + off0) = __halves2half2(l0, l1);
                *(__half2*)(ahi + off1) = __halves2half2(h2v, h3);
                *(__half2*)(alo + off1) = __halves2half2(l2, l3);
            }
    }
}

// =====================================================================
// Final RMS norm: out = y * g_out * 32 / max(||y||, eps)
// =====================================================================
__global__ __launch_bounds__(256) void final_norm_kernel(
    const float* __restrict__ in, const float* __restrict__ g, float* __restrict__ outp)
{
    long row = blockIdx.x;
    const float* p = in + row * (long)DM;
    int c = threadIdx.x * 4;
    float4 v = *(const float4*)(p + c);
    float s = v.x * v.x + v.y * v.y + v.z * v.z + v.w * v.w;
#pragma unroll
    for (int m = 16; m; m >>= 1) s += __shfl_xor_sync(0xffffffffu, s, m);
    __shared__ float ws[8];
    __shared__ float fac;
    int w = threadIdx.x >> 5;
    if ((threadIdx.x & 31) == 0) ws[w] = s;
    __syncthreads();
    if (threadIdx.x == 0) {
        float a = 0.f;
#pragma unroll
        for (int i = 0; i < 8; i++) a += ws[i];
        fac = 32.0f / fmaxf(sqrtf(a), 1e-12f);
    }
    __syncthreads();
    float f = fac;
    float4 g4 = *(const float4*)(g + c);
    float4 o = make_float4(v.x * f * g4.x, v.y * f * g4.y, v.z * f * g4.z, v.w * f * g4.w);
    *(float4*)(outp + row * (long)DM + c) = o;
}

// =====================================================================
// launch
// =====================================================================
extern "C" void kernel_launch(void* const* d_in, const int* in_sizes, int n_in,
                              void* d_out, int out_size)
{
    const float* x    = (const float*)d_in[0];
    const float* Wqkv = (const float*)d_in[1];
    const float* bqkv = (const float*)d_in[2];
    const float* Wout = (const float*)d_in[3];
    const float* bout = (const float*)d_in[4];
    const float* gq   = (const float*)d_in[5];
    const float* gk   = (const float*)d_in[6];
    const float* gout = (const float*)d_in[7];
    float* out = (float*)d_out;

    float *qkv, *prj;
    __half *xhi, *xlo, *whi, *wlo, *wohi, *wolo;
    __half *Qhi, *Qlo, *Khi, *Klo, *Ahi, *Alo, *Vthi, *Vtlo;
    cudaGetSymbolAddress((void**)&qkv, g_qkv);
    cudaGetSymbolAddress((void**)&prj, g_prj);
    cudaGetSymbolAddress((void**)&xhi, g_xhi);   cudaGetSymbolAddress((void**)&xlo, g_xlo);
    cudaGetSymbolAddress((void**)&whi, g_whi);   cudaGetSymbolAddress((void**)&wlo, g_wlo);
    cudaGetSymbolAddress((void**)&wohi, g_wohi); cudaGetSymbolAddress((void**)&wolo, g_wolo);
    cudaGetSymbolAddress((void**)&Qhi, g_qhi);   cudaGetSymbolAddress((void**)&Qlo, g_qlo);
    cudaGetSymbolAddress((void**)&Khi, g_khi);   cudaGetSymbolAddress((void**)&Klo, g_klo);
    cudaGetSymbolAddress((void**)&Ahi, g_ahi);   cudaGetSymbolAddress((void**)&Alo, g_alo);
    cudaGetSymbolAddress((void**)&Vthi, g_vthi); cudaGetSymbolAddress((void**)&Vtlo, g_vtlo);

    cudaFuncSetAttribute(gemm_mma, cudaFuncAttributeMaxDynamicSharedMemorySize, GM_SMEM);
    cudaFuncSetAttribute(attn_mma, cudaFuncAttributeMaxDynamicSharedMemorySize, AT_SMEM);

    // 0) fp32 -> fp16 hi/lo splits
    long n_x = (long)MR * DM / 4, n_w = (long)N3 * DM / 4, n_wo = (long)DM * DM / 4;
    conv_hilo<<<(unsigned)((n_x  + 255) / 256), 256>>>(x,    xhi,  xlo,  n_x);
    conv_hilo<<<(unsigned)((n_w  + 255) / 256), 256>>>(Wqkv, whi,  wlo,  n_w);
    conv_hilo<<<(unsigned)((n_wo + 255) / 256), 256>>>(Wout, wohi, wolo, n_wo);

    // 1) QKV projection
    gemm_mma<<<dim3(N3 / 128, MR / 128), 256, GM_SMEM>>>(xhi, xlo, whi, wlo, bqkv, qkv, N3, DM);

    // 2) q/k norm -> fp16 hi/lo ; V -> transposed fp16 hi/lo
    qk_norm<<<MR, 256>>>(qkv, gq, gk, Qhi, Qlo, Khi, Klo);
    v_trans<<<dim3(LL / 128, BB * NH), 256>>>(qkv, Vthi, Vtlo);

    // 3) attention (register-P FA2, validated R12)
    attn_mma<<<dim3(LL / 128, BB * NH), 256, AT_SMEM>>>(Qhi, Qlo, Khi, Klo, Vthi, Vtlo, Ahi, Alo);

    // 4) output projection
    gemm_mma<<<dim3(DM / 128, MR / 128), 256, GM_SMEM>>>(Ahi, Alo, wohi, wolo, bout, prj, DM, DM);

    // 5) final RMS norm -> d_out
    final_norm_kernel<<<MR, 256>>>(prj, gout, out);
}

// round 15
// speedup vs baseline: 1.5989x; 1.0437x over previous
#include <cuda_runtime.h>
#include <cuda_fp16.h>

typedef unsigned int u32;
typedef unsigned long long u64;

// ---------------- problem constants ----------------
#define BB 4
#define LL 2048
#define DM 1024
#define NH 16
#define MR 8192
#define N3 3072

// ---------------- scratch (device globals; allocation is forbidden) ----------------
__device__ float g_qkv[(size_t)MR * N3];
__device__ float g_prj[(size_t)MR * DM];
__device__ __half g_xhi[(size_t)MR * DM],  g_xlo[(size_t)MR * DM];
__device__ __half g_whi[(size_t)N3 * DM],  g_wlo[(size_t)N3 * DM];
__device__ __half g_wohi[(size_t)DM * DM], g_wolo[(size_t)DM * DM];
__device__ __half g_qhi[(size_t)MR * DM],  g_qlo[(size_t)MR * DM];
__device__ __half g_khi[(size_t)MR * DM],  g_klo[(size_t)MR * DM];
__device__ __half g_ahi[(size_t)MR * DM],  g_alo[(size_t)MR * DM];
__device__ __half g_vthi[(size_t)BB * NH * 64 * LL], g_vtlo[(size_t)BB * NH * 64 * LL];

// ---------------- portable PTX helpers ----------------
__device__ __forceinline__ u32 smem_u32(const void* p) {
    u32 a;
    asm("{ .reg .u64 t; cvta.to.shared.u64 t, %1; cvt.u32.u64 %0, t; }" : "=r"(a) : "l"(p));
    return a;
}
__device__ __forceinline__ void ldsm4(u32& r0, u32& r1, u32& r2, u32& r3, u32 a) {
    asm volatile("ldmatrix.sync.aligned.m8n8.x4.shared.b16 {%0,%1,%2,%3},[%4];"
                 : "=r"(r0), "=r"(r1), "=r"(r2), "=r"(r3) : "r"(a));
}
__device__ __forceinline__ void ldsm2(u32& r0, u32& r1, u32 a) {
    asm volatile("ldmatrix.sync.aligned.m8n8.x2.shared.b16 {%0,%1},[%2];"
                 : "=r"(r0), "=r"(r1) : "r"(a));
}
__device__ __forceinline__ void mma16(float* c, const u32* a, const u32* b) {
    asm volatile("mma.sync.aligned.m16n8k16.row.col.f32.f16.f16.f32 "
                 "{%0,%1,%2,%3},{%4,%5,%6,%7},{%8,%9},{%0,%1,%2,%3};"
                 : "+f"(c[0]), "+f"(c[1]), "+f"(c[2]), "+f"(c[3])
                 : "r"(a[0]), "r"(a[1]), "r"(a[2]), "r"(a[3]), "r"(b[0]), "r"(b[1]));
}
__device__ __forceinline__ float ex2f(float x) {
    float y; asm("ex2.approx.f32 %0,%1;" : "=f"(y) : "f"(x)); return y;
}
__device__ __forceinline__ u32 h2pk(float a, float b) {
    __half2 t = __float22half2_rn(make_float2(a, b));
    return *(u32*)&t;
}
#define CPA16(d, s) asm volatile("cp.async.cg.shared.global [%0],[%1],16;" :: "r"(d), "l"(s) : "memory")
#define CPC()       asm volatile("cp.async.commit_group;" ::: "memory")
#define CPW(n)      asm volatile("cp.async.wait_group %0;" :: "n"(n) : "memory")

// =====================================================================
// fp32 -> fp16 hi/lo planar split
// =====================================================================
__global__ __launch_bounds__(256) void conv_hilo(
    const float* __restrict__ src, __half* __restrict__ hi,
    __half* __restrict__ lo, long n4)
{
    long i = (long)blockIdx.x * 256 + threadIdx.x;
    if (i >= n4) return;
    float4 v = ((const float4*)src)[i];
    float f[4] = { v.x, v.y, v.z, v.w };
    __half h[4], l[4];
#pragma unroll
    for (int e = 0; e < 4; e++) {
        h[e] = __float2half_rn(f[e]);
        l[e] = __float2half_rn(f[e] - __half2float(h[e]));
    }
    ((uint2*)hi)[i] = *(uint2*)h;
    ((uint2*)lo)[i] = *(uint2*)l;
}

// =====================================================================
// HMMA TN GEMM, fp16 hi/lo (3 products) — unchanged from R13 (passing).
// =====================================================================
#define GSTR 40
#define GPL  5120
#define GBUF 20480
#define GM_SMEM (2 * GBUF * 2)

__global__ __launch_bounds__(256, 2) void gemm_mma(
    const __half* __restrict__ Ahi, const __half* __restrict__ Alo,
    const __half* __restrict__ Bhi, const __half* __restrict__ Blo,
    const float* __restrict__ bias, float* __restrict__ C, int N, int K)
{
    extern __shared__ __half sh[];
    const u32 sb = smem_u32(sh);
    const int tid = threadIdx.x, w = tid >> 5, lane = tid & 31;
    const int bm = blockIdx.y * 128, bn = blockIdx.x * 128;
    const int wm = (w >> 2) * 64, wn = (w & 3) * 32;

    float acc[4][4][4];
#pragma unroll
    for (int mt = 0; mt < 4; mt++)
#pragma unroll
        for (int nt = 0; nt < 4; nt++)
#pragma unroll
            for (int r = 0; r < 4; r++) acc[mt][nt][r] = 0.f;

    const int pl = tid >> 6, lu = tid & 63, ls = lu & 3, lr0 = lu >> 2;
    const __half* lbase = ((pl == 0) ? Ahi : (pl == 1) ? Alo : (pl == 2) ? Bhi : Blo)
                          + (long)((pl < 2 ? bm : bn) + lr0) * K + ls * 8;
    const u32 ldst0 = (u32)((pl * GPL + lr0 * GSTR + ls * 8) * 2);
    const long lrowstride = (long)16 * K;

    const int nch = K / 32;
#pragma unroll
    for (int it = 0; it < 8; it++) CPA16(sb + ldst0 + it * (16 * GSTR * 2), lbase + it * lrowstride);
    CPC();

    for (int c = 0; c < nch; c++) {
        if (c + 1 < nch) {
            u32 bo = (u32)(((c + 1) & 1) * GBUF * 2);
            const __half* src = lbase + (c + 1) * 32;
#pragma unroll
            for (int it = 0; it < 8; it++) CPA16(sb + bo + ldst0 + it * (16 * GSTR * 2), src + it * lrowstride);
            CPC();
            CPW(1);
        } else {
            CPW(0);
        }
        __syncthreads();
        u32 base = sb + (u32)((c & 1) * GBUF * 2);
#pragma unroll
        for (int ks = 0; ks < 2; ks++) {
            u32 ah[4][4], al[4][4], bh[4][2], bl[4][2];
#pragma unroll
            for (int mt = 0; mt < 4; mt++) {
                u32 ra = base + (u32)(((wm + mt * 16 + (lane & 15)) * GSTR +
                                       ks * 16 + ((lane >> 4) & 1) * 8) * 2);
                ldsm4(ah[mt][0], ah[mt][1], ah[mt][2], ah[mt][3], ra);
                ldsm4(al[mt][0], al[mt][1], al[mt][2], al[mt][3], ra + GPL * 2);
            }
#pragma unroll
            for (int nt = 0; nt < 4; nt++) {
                u32 rb = base + (u32)((2 * GPL + (wn + nt * 8 + (lane & 7)) * GSTR +
                                       ks * 16 + ((lane >> 3) & 1) * 8) * 2);
                ldsm2(bh[nt][0], bh[nt][1], rb);
                ldsm2(bl[nt][0], bl[nt][1], rb + GPL * 2);
            }
#pragma unroll
            for (int mt = 0; mt < 4; mt++)
#pragma unroll
                for (int nt = 0; nt < 4; nt++) {
                    mma16(acc[mt][nt], ah[mt], bh[nt]);
                    mma16(acc[mt][nt], ah[mt], bl[nt]);
                    mma16(acc[mt][nt], al[mt], bh[nt]);
                }
        }
        __syncthreads();   // race guard: buf[(c-1)&1] reads done before prefetch writes in c+1
    }
    // epilogue
#pragma unroll
    for (int mt = 0; mt < 4; mt++) {
        int r0 = bm + wm + mt * 16 + (lane >> 2);
#pragma unroll
        for (int nt = 0; nt < 4; nt++) {
            int cb = bn + wn + nt * 8 + 2 * (lane & 3);
            float2 bv = *(const float2*)(bias + cb);
            float2 o0 = make_float2(acc[mt][nt][0] + bv.x, acc[mt][nt][1] + bv.y);
            float2 o1 = make_float2(acc[mt][nt][2] + bv.x, acc[mt][nt][3] + bv.y);
            *(float2*)(C + (long)r0 * N + cb) = o0;
            *(float2*)(C + (long)(r0 + 8) * N + cb) = o1;
        }
    }
}

// =====================================================================
// q/k RMS norm -> fp16 hi/lo (unchanged)
// =====================================================================
__global__ __launch_bounds__(256) void qk_norm(
    const float* __restrict__ qkv,
    const float* __restrict__ gq, const float* __restrict__ gk,
    __half* __restrict__ qhi, __half* __restrict__ qlo,
    __half* __restrict__ khi, __half* __restrict__ klo)
{
    long row = blockIdx.x;
    const float* p = qkv + row * (long)N3;
    int c = threadIdx.x * 4;
    float4 q4 = *(const float4*)(p + c);
    float4 k4 = *(const float4*)(p + DM + c);
    float sq = q4.x * q4.x + q4.y * q4.y + q4.z * q4.z + q4.w * q4.w;
    float sk = k4.x * k4.x + k4.y * k4.y + k4.z * k4.z + k4.w * k4.w;
#pragma unroll
    for (int m = 16; m; m >>= 1) {
        sq += __shfl_xor_sync(0xffffffffu, sq, m);
        sk += __shfl_xor_sync(0xffffffffu, sk, m);
    }
    __shared__ float2 ws[8];
    __shared__ float2 fac;
    int w = threadIdx.x >> 5;
    if ((threadIdx.x & 31) == 0) ws[w] = make_float2(sq, sk);
    __syncthreads();
    if (threadIdx.x == 0) {
        float a = 0.f, bsum = 0.f;
#pragma unroll
        for (int i = 0; i < 8; i++) { a += ws[i].x; bsum += ws[i].y; }
        fac = make_float2(5.770780163555851f / fmaxf(sqrtf(a), 1e-12f),   // 4*log2(e)
                          32.0f / fmaxf(sqrtf(bsum), 1e-12f));
    }
    __syncthreads();
    float fq = fac.x, fk = fac.y;
    float4 gq4 = *(const float4*)(gq + c);
    float4 gk4 = *(const float4*)(gk + c);
    float qs[4] = { q4.x * fq * gq4.x, q4.y * fq * gq4.y, q4.z * fq * gq4.z, q4.w * fq * gq4.w };
    float ks[4] = { k4.x * fk * gk4.x, k4.y * fk * gk4.y, k4.z * fk * gk4.z, k4.w * fk * gk4.w };
    __half qh[4], ql[4], kh[4], kl[4];
#pragma unroll
    for (int e = 0; e < 4; e++) {
        qh[e] = __float2half_rn(qs[e]); ql[e] = __float2half_rn(qs[e] - __half2float(qh[e]));
        kh[e] = __float2half_rn(ks[e]); kl[e] = __float2half_rn(ks[e] - __half2float(kh[e]));
    }
    long o = row * (long)DM + c;
    *(uint2*)(qhi + o) = *(uint2*)qh;  *(uint2*)(qlo + o) = *(uint2*)ql;
    *(uint2*)(khi + o) = *(uint2*)kh;  *(uint2*)(klo + o) = *(uint2*)kl;
}

// =====================================================================
// V transpose (unchanged)
// =====================================================================
#define VT_STR 136
__global__ __launch_bounds__(256) void v_trans(
    const float* __restrict__ qkv, __half* __restrict__ vthi, __half* __restrict__ vtlo)
{
    __shared__ __half shi[64 * VT_STR], slo[64 * VT_STR];
    int bh = blockIdx.y, b = bh >> 4, h = bh & 15;
    int l0 = blockIdx.x * 128;
    int tid = threadIdx.x;
#pragma unroll
    for (int it = 0; it < 8; it++) {
        int idx = it * 256 + tid;
        int l = idx >> 4, d4 = (idx & 15) * 4;
        float4 v = *(const float4*)(qkv + ((long)(b * LL + l0 + l)) * N3 + 2 * DM + h * 64 + d4);
        float f[4] = { v.x, v.y, v.z, v.w };
#pragma unroll
        for (int e = 0; e < 4; e++) {
            __half hv = __float2half_rn(f[e]);
            __half lv = __float2half_rn(f[e] - __half2float(hv));
            shi[(d4 + e) * VT_STR + l] = hv;
            slo[(d4 + e) * VT_STR + l] = lv;
        }
    }
    __syncthreads();
#pragma unroll
    for (int it = 0; it < 8; it++) {
        int i = it * 256 + tid;
        int pl = i >> 10, j = i & 1023;
        int d = j >> 4, s = j & 15;
        uint4 v = *(uint4*)&((pl ? slo : shi)[d * VT_STR + s * 8]);
        *(uint4*)((pl ? vtlo : vthi) + ((long)bh * 64 + d) * LL + l0 + s * 8) = v;
    }
}

// =====================================================================
// HMMA flash attention, register-P + PER-HALF INDEPENDENT SOFTMAX.
// Each key-half warp keeps its own (m, l, O); no per-chunk cross-half
// max exchange -> ONE block barrier per chunk. Epilogue combines:
//   m* = max(m0,m1), f_h = 2^(m_h-m*), O = (O0 f0 + O1 f1)/(l0 f0 + l1 f1)
// smem (halves): QHI 0, QLO 9216, KV0 18432, KV1 36864
// floats: msum[2][128] @ byte 110592, lsum[2][128] after it.
// O-combine region (floats, stride 68) reuses KV space @ byte 36864.
// =====================================================================
#define AKV0 18432
#define AKV1 36864
#define ARED_B 110592
#define AT_SMEM (110592 + 2048)

__global__ __launch_bounds__(256) void attn_mma(
    const __half* __restrict__ qhi, const __half* __restrict__ qlo,
    const __half* __restrict__ khi, const __half* __restrict__ klo,
    const __half* __restrict__ vthi, const __half* __restrict__ vtlo,
    __half* __restrict__ ahi, __half* __restrict__ alo)
{
    extern __shared__ __half sh[];
    const u32 sb = smem_u32(sh);
    const int tid = threadIdx.x, w = tid >> 5, lane = tid & 31;
    const int bh = blockIdx.y, b = bh >> 4, hd = bh & 15;
    const int q0 = blockIdx.x * 128;
    const int wg = w >> 1, wn = w & 1;
    float* msum = (float*)((char*)sh + ARED_B);   // [wn][128]
    float* lsum = msum + 256;                     // [wn][128]
    float* ocmb = (float*)((char*)sh + AKV0 * 2); // [128][68]

    // Q loader
    {
        const int pl = tid >> 7, u = tid & 127, s = u & 7, r0 = u >> 3;
        const __half* qb = (pl ? qlo : qhi) + ((long)(b * LL + q0 + r0)) * DM + hd * 64 + s * 8;
        u32 d0 = sb + (u32)((pl * 9216 + r0 * 72 + s * 8) * 2);
#pragma unroll
        for (int it = 0; it < 8; it++) CPA16(d0 + it * (16 * 72 * 2), qb + (long)it * 16 * DM);
        CPC();
    }
    // KV loader state
    const int kpl = tid >> 6, ku = tid & 63, kls = ku & 7, klr0 = ku >> 3;
    const __half* kvb;
    long kvstep;
    if (kpl == 0)      { kvb = khi  + ((long)(b * LL + klr0)) * DM + hd * 64 + kls * 8; kvstep = (long)8 * DM; }
    else if (kpl == 1) { kvb = klo  + ((long)(b * LL + klr0)) * DM + hd * 64 + kls * 8; kvstep = (long)8 * DM; }
    else if (kpl == 2) { kvb = vthi + ((long)(bh * 64 + klr0)) * LL + kls * 8;          kvstep = (long)8 * LL; }
    else               { kvb = vtlo + ((long)(bh * 64 + klr0)) * LL + kls * 8;          kvstep = (long)8 * LL; }
    const long kvchunk = (kpl < 2) ? (long)64 * DM : 64;
    const u32 kdst0 = (u32)((kpl * 4608 + klr0 * 72 + kls * 8) * 2);

#pragma unroll
    for (int it = 0; it < 8; it++) CPA16(sb + AKV0 * 2 + kdst0 + it * (8 * 72 * 2), kvb + it * kvstep);
    CPC();

    float o[2][8][4];
#pragma unroll
    for (int mt = 0; mt < 2; mt++)
#pragma unroll
        for (int dt = 0; dt < 8; dt++)
#pragma unroll
            for (int r = 0; r < 4; r++) o[mt][dt][r] = 0.f;
    float mr[4] = { -1e30f, -1e30f, -1e30f, -1e30f }, lr[4] = { 0.f, 0.f, 0.f, 0.f };

    for (int c = 0; c < 32; c++) {
        CPW(0);
        __syncthreads();   // single per-chunk barrier (KV buffer handoff + race guard)
        if (c + 1 < 32) {
            u32 bo = (u32)(((c + 1) & 1) ? AKV1 * 2 : AKV0 * 2);
            const __half* src = kvb + (c + 1) * kvchunk;
#pragma unroll
            for (int it = 0; it < 8; it++) CPA16(sb + bo + kdst0 + it * (8 * 72 * 2), src + it * kvstep);
            CPC();
        }
        const u32 AKVB = (u32)((c & 1) ? AKV1 : AKV0);

        // ---- S = Q K^T (3 products), warp: rows wg*32..+32, keys wn*32..+32 ----
        float s[2][4][4];
#pragma unroll
        for (int mt = 0; mt < 2; mt++)
#pragma unroll
            for (int nt = 0; nt < 4; nt++)
#pragma unroll
                for (int r = 0; r < 4; r++) s[mt][nt][r] = 0.f;
#pragma unroll
        for (int ks = 0; ks < 4; ks++) {
            u32 qh_[2][4], ql_[2][4], kh_[4][2], kl_[4][2];
#pragma unroll
            for (int mt = 0; mt < 2; mt++) {
                u32 ra = sb + (u32)(((wg * 32 + mt * 16 + (lane & 15)) * 72 +
                                     ks * 16 + ((lane >> 4) & 1) * 8) * 2);
                ldsm4(qh_[mt][0], qh_[mt][1], qh_[mt][2], qh_[mt][3], ra);
                ldsm4(ql_[mt][0], ql_[mt][1], ql_[mt][2], ql_[mt][3], ra + 9216 * 2);
            }
#pragma unroll
            for (int nt = 0; nt < 4; nt++) {
                u32 rb = sb + (u32)((AKVB + (wn * 32 + nt * 8 + (lane & 7)) * 72 +
                                     ks * 16 + ((lane >> 3) & 1) * 8) * 2);
                ldsm2(kh_[nt][0], kh_[nt][1], rb);
                ldsm2(kl_[nt][0], kl_[nt][1], rb + 4608 * 2);
            }
#pragma unroll
            for (int mt = 0; mt < 2; mt++)
#pragma unroll
                for (int nt = 0; nt < 4; nt++) {
                    mma16(s[mt][nt], qh_[mt], kh_[nt]);
                    mma16(s[mt][nt], qh_[mt], kl_[nt]);
                    mma16(s[mt][nt], ql_[mt], kh_[nt]);
                }
        }

        // ---- warp-local online softmax (no cross-half exchange) ----
        float alpha[4], ssum[4];
#pragma unroll
        for (int mt = 0; mt < 2; mt++)
#pragma unroll
            for (int hh = 0; hh < 2; hh++) {
                int slot = mt * 2 + hh;
                float mx = -1e30f;
#pragma unroll
                for (int nt = 0; nt < 4; nt++) {
                    mx = fmaxf(mx, s[mt][nt][hh * 2]);
                    mx = fmaxf(mx, s[mt][nt][hh * 2 + 1]);
                }
                mx = fmaxf(mx, __shfl_xor_sync(0xffffffffu, mx, 1));
                mx = fmaxf(mx, __shfl_xor_sync(0xffffffffu, mx, 2));
                float mn = fmaxf(mr[slot], mx);
                alpha[slot] = ex2f(mr[slot] - mn);
                mr[slot] = mn;
            }
        // exponentiate in place; accumulate lane-local sums
#pragma unroll
        for (int mt = 0; mt < 2; mt++) {
            float s0 = 0.f, s1 = 0.f;
#pragma unroll
            for (int nt = 0; nt < 4; nt++) {
                s[mt][nt][0] = ex2f(s[mt][nt][0] - mr[mt * 2]);
                s[mt][nt][1] = ex2f(s[mt][nt][1] - mr[mt * 2]);
                s[mt][nt][2] = ex2f(s[mt][nt][2] - mr[mt * 2 + 1]);
                s[mt][nt][3] = ex2f(s[mt][nt][3] - mr[mt * 2 + 1]);
                s0 += s[mt][nt][0] + s[mt][nt][1];
                s1 += s[mt][nt][2] + s[mt][nt][3];
            }
            ssum[mt * 2] = s0; ssum[mt * 2 + 1] = s1;
        }
        // O rescale (before PV accumulates)
#pragma unroll
        for (int mt = 0; mt < 2; mt++)
#pragma unroll
            for (int dt = 0; dt < 8; dt++) {
                o[mt][dt][0] *= alpha[mt * 2];     o[mt][dt][1] *= alpha[mt * 2];
                o[mt][dt][2] *= alpha[mt * 2 + 1]; o[mt][dt][3] *= alpha[mt * 2 + 1];
            }
        // pack P a-frags from S c-frags
        u32 aP[2][2][4];
#pragma unroll
        for (int mt = 0; mt < 2; mt++)
#pragma unroll
            for (int ksl = 0; ksl < 2; ksl++) {
                aP[mt][ksl][0] = h2pk(s[mt][2 * ksl][0],     s[mt][2 * ksl][1]);
                aP[mt][ksl][1] = h2pk(s[mt][2 * ksl][2],     s[mt][2 * ksl][3]);
                aP[mt][ksl][2] = h2pk(s[mt][2 * ksl + 1][0], s[mt][2 * ksl + 1][1]);
                aP[mt][ksl][3] = h2pk(s[mt][2 * ksl + 1][2], s[mt][2 * ksl + 1][3]);
            }
        // ---- O += P V (feed tensor pipe before the l shuffles) ----
#pragma unroll
        for (int ksl = 0; ksl < 2; ksl++) {
            u32 vh_[8][2], vl_[8][2];
#pragma unroll
            for (int dt = 0; dt < 8; dt++) {
                u32 rb = sb + (u32)((AKVB + 9216 + (dt * 8 + (lane & 7)) * 72 +
                                     wn * 32 + ksl * 16 + ((lane >> 3) & 1) * 8) * 2);
                ldsm2(vh_[dt][0], vh_[dt][1], rb);
                ldsm2(vl_[dt][0], vl_[dt][1], rb + 4608 * 2);
            }
#pragma unroll
            for (int mt = 0; mt < 2; mt++)
#pragma unroll
                for (int dt = 0; dt < 8; dt++) {
                    mma16(o[mt][dt], aP[mt][ksl], vh_[dt]);
                    mma16(o[mt][dt], aP[mt][ksl], vl_[dt]);
                }
        }
        // l update (deferred shuffles; tensor pipe already busy)
#pragma unroll
        for (int slot = 0; slot < 4; slot++) {
            float sv = ssum[slot];
            sv += __shfl_xor_sync(0xffffffffu, sv, 1);
            sv += __shfl_xor_sync(0xffffffffu, sv, 2);
            lr[slot] = lr[slot] * alpha[slot] + sv;
        }
    }

    // ---- epilogue: combine halves with per-half (m, l, O) ----
    __syncthreads();   // all PV done; KV smem free
#pragma unroll
    for (int mt = 0; mt < 2; mt++)
#pragma unroll
        for (int hh = 0; hh < 2; hh++) {
            int slot = mt * 2 + hh;
            if ((lane & 3) == 0) {
                int row = wg * 32 + mt * 16 + hh * 8 + (lane >> 2);
                msum[wn * 128 + row] = mr[slot];
                lsum[wn * 128 + row] = lr[slot];
            }
        }
    if (wn == 1) {
#pragma unroll
        for (int mt = 0; mt < 2; mt++)
#pragma unroll
            for (int dt = 0; dt < 8; dt++) {
                int r = wg * 32 + mt * 16 + (lane >> 2);
                int cc = dt * 8 + (lane & 3) * 2;
                *(float2*)&ocmb[r * 68 + cc]       = make_float2(o[mt][dt][0], o[mt][dt][1]);
                *(float2*)&ocmb[(r + 8) * 68 + cc] = make_float2(o[mt][dt][2], o[mt][dt][3]);
            }
    }
    __syncthreads();
    if (wn == 0) {
        float fa0[4], fa1[4];
#pragma unroll
        for (int mt = 0; mt < 2; mt++)
#pragma unroll
            for (int hh = 0; hh < 2; hh++) {
                int slot = mt * 2 + hh;
                int row = wg * 32 + mt * 16 + hh * 8 + (lane >> 2);
                float m1 = msum[128 + row], l1 = lsum[128 + row];
                float ms = fmaxf(mr[slot], m1);
                float f0 = ex2f(mr[slot] - ms), f1 = ex2f(m1 - ms);
                float inv = 1.0f / (lr[slot] * f0 + l1 * f1);
                fa0[slot] = f0 * inv;
                fa1[slot] = f1 * inv;
            }
#pragma unroll
        for (int mt = 0; mt < 2; mt++)
#pragma unroll
            for (int dt = 0; dt < 8; dt++) {
                int r = wg * 32 + mt * 16 + (lane >> 2);
                int cc = dt * 8 + (lane & 3) * 2;
                float2 p0 = *(float2*)&ocmb[r * 68 + cc];
                float2 p1 = *(float2*)&ocmb[(r + 8) * 68 + cc];
                float v0 = o[mt][dt][0] * fa0[mt * 2]     + p0.x * fa1[mt * 2];
                float v1 = o[mt][dt][1] * fa0[mt * 2]     + p0.y * fa1[mt * 2];
                float v2 = o[mt][dt][2] * fa0[mt * 2 + 1] + p1.x * fa1[mt * 2 + 1];
                float v3 = o[mt][dt][3] * fa0[mt * 2 + 1] + p1.y * fa1[mt * 2 + 1];
                __half h0 = __float2half_rn(v0), h1 = __float2half_rn(v1);
                __half h2v = __float2half_rn(v2), h3 = __float2half_rn(v3);
                __half l0 = __float2half_rn(v0 - __half2float(h0));
                __half l1 = __float2half_rn(v1 - __half2float(h1));
                __half l2 = __float2half_rn(v2 - __half2float(h2v));
                __half l3 = __float2half_rn(v3 - __half2float(h3));
                long off0 = ((long)(b * LL + q0 + r)) * DM + hd * 64 + cc;
                long off1 = ((long)(b * LL + q0 + r + 8)) * DM + hd * 64 + cc;
                *(__half2*)(ahi + off0) = __halves2half2(h0, h1);
                *(__half2*)(alo + off0) = __halves2half2(l0, l1);
                *(__half2*)(ahi + off1) = __halves2half2(h2v, h3);
                *(__half2*)(alo + off1) = __halves2half2(l2, l3);
            }
    }
}

// =====================================================================
// Final RMS norm (unchanged)
// =====================================================================
__global__ __launch_bounds__(256) void final_norm_kernel(
    const float* __restrict__ in, const float* __restrict__ g, float* __restrict__ outp)
{
    long row = blockIdx.x;
    const float* p = in + row * (long)DM;
    int c = threadIdx.x * 4;
    float4 v = *(const float4*)(p + c);
    float s = v.x * v.x + v.y * v.y + v.z * v.z + v.w * v.w;
#pragma unroll
    for (int m = 16; m; m >>= 1) s += __shfl_xor_sync(0xffffffffu, s, m);
    __shared__ float ws[8];
    __shared__ float fac;
    int w = threadIdx.x >> 5;
    if ((threadIdx.x & 31) == 0) ws[w] = s;
    __syncthreads();
    if (threadIdx.x == 0) {
        float a = 0.f;
#pragma unroll
        for (int i = 0; i < 8; i++) a += ws[i];
        fac = 32.0f / fmaxf(sqrtf(a), 1e-12f);
    }
    __syncthreads();
    float f = fac;
    float4 g4 = *(const float4*)(g + c);
    float4 o = make_float4(v.x * f * g4.x, v.y * f * g4.y, v.z * f * g4.z, v.w * f * g4.w);
    *(float4*)(outp + row * (long)DM + c) = o;
}

// =====================================================================
// launch
// =====================================================================
extern "C" void kernel_launch(void* const* d_in, const int* in_sizes, int n_in,
                              void* d_out, int out_size)
{
    const float* x    = (const float*)d_in[0];
    const float* Wqkv = (const float*)d_in[1];
    const float* bqkv = (const float*)d_in[2];
    const float* Wout = (const float*)d_in[3];
    const float* bout = (const float*)d_in[4];
    const float* gq   = (const float*)d_in[5];
    const float* gk   = (const float*)d_in[6];
    const float* gout = (const float*)d_in[7];
    float* out = (float*)d_out;

    float *qkv, *prj;
    __half *xhi, *xlo, *whi, *wlo, *wohi, *wolo;
    __half *Qhi, *Qlo, *Khi, *Klo, *Ahi, *Alo, *Vthi, *Vtlo;
    cudaGetSymbolAddress((void**)&qkv, g_qkv);
    cudaGetSymbolAddress((void**)&prj, g_prj);
    cudaGetSymbolAddress((void**)&xhi, g_xhi);   cudaGetSymbolAddress((void**)&xlo, g_xlo);
    cudaGetSymbolAddress((void**)&whi, g_whi);   cudaGetSymbolAddress((void**)&wlo, g_wlo);
    cudaGetSymbolAddress((void**)&wohi, g_wohi); cudaGetSymbolAddress((void**)&wolo, g_wolo);
    cudaGetSymbolAddress((void**)&Qhi, g_qhi);   cudaGetSymbolAddress((void**)&Qlo, g_qlo);
    cudaGetSymbolAddress((void**)&Khi, g_khi);   cudaGetSymbolAddress((void**)&Klo, g_klo);
    cudaGetSymbolAddress((void**)&Ahi, g_ahi);   cudaGetSymbolAddress((void**)&Alo, g_alo);
    cudaGetSymbolAddress((void**)&Vthi, g_vthi); cudaGetSymbolAddress((void**)&Vtlo, g_vtlo);

    cudaFuncSetAttribute(gemm_mma, cudaFuncAttributeMaxDynamicSharedMemorySize, GM_SMEM);
    cudaFuncSetAttribute(attn_mma, cudaFuncAttributeMaxDynamicSharedMemorySize, AT_SMEM);

    // 0) fp32 -> fp16 hi/lo splits
    long n_x = (long)MR * DM / 4, n_w = (long)N3 * DM / 4, n_wo = (long)DM * DM / 4;
    conv_hilo<<<(unsigned)((n_x  + 255) / 256), 256>>>(x,    xhi,  xlo,  n_x);
    conv_hilo<<<(unsigned)((n_w  + 255) / 256), 256>>>(Wqkv, whi,  wlo,  n_w);
    conv_hilo<<<(unsigned)((n_wo + 255) / 256), 256>>>(Wout, wohi, wolo, n_wo);

    // 1) QKV projection
    gemm_mma<<<dim3(N3 / 128, MR / 128), 256, GM_SMEM>>>(xhi, xlo, whi, wlo, bqkv, qkv, N3, DM);

    // 2) q/k norm -> fp16 hi/lo ; V -> transposed fp16 hi/lo
    qk_norm<<<MR, 256>>>(qkv, gq, gk, Qhi, Qlo, Khi, Klo);
    v_trans<<<dim3(LL / 128, BB * NH), 256>>>(qkv, Vthi, Vtlo);

    // 3) attention (register-P FA2, per-half softmax)
    attn_mma<<<dim3(LL / 128, BB * NH), 256, AT_SMEM>>>(Qhi, Qlo, Khi, Klo, Vthi, Vtlo, Ahi, Alo);

    // 4) output projection
    gemm_mma<<<dim3(DM / 128, MR / 128), 256, GM_SMEM>>>(Ahi, Alo, wohi, wolo, bout, prj, DM, DM);

    // 5) final RMS norm -> d_out
    final_norm_kernel<<<MR, 256>>>(prj, gout, out);
}

// round 17
// speedup vs baseline: 1.7983x; 1.1248x over previous
#include <cuda_runtime.h>
#include <cuda_fp16.h>

typedef unsigned int u32;
typedef unsigned long long u64;

// ---------------- problem constants ----------------
#define BB 4
#define LL 2048
#define DM 1024
#define NH 16
#define MR 8192
#define N3 3072

// ---------------- scratch (device globals; allocation is forbidden) ----------------
__device__ float g_qkv[(size_t)MR * N3];
__device__ float g_prj[(size_t)MR * DM];
__device__ __half g_xhi[(size_t)MR * DM],  g_xlo[(size_t)MR * DM];
__device__ __half g_whi[(size_t)N3 * DM],  g_wlo[(size_t)N3 * DM];
__device__ __half g_wohi[(size_t)DM * DM], g_wolo[(size_t)DM * DM];
__device__ __half g_qhi[(size_t)MR * DM],  g_qlo[(size_t)MR * DM];
__device__ __half g_khi[(size_t)MR * DM],  g_klo[(size_t)MR * DM];
__device__ __half g_ahi[(size_t)MR * DM],  g_alo[(size_t)MR * DM];
__device__ __half g_vthi[(size_t)BB * NH * 64 * LL];

// ---------------- portable PTX helpers ----------------
__device__ __forceinline__ u32 smem_u32(const void* p) {
    u32 a;
    asm("{ .reg .u64 t; cvta.to.shared.u64 t, %1; cvt.u32.u64 %0, t; }" : "=r"(a) : "l"(p));
    return a;
}
__device__ __forceinline__ void ldsm4(u32& r0, u32& r1, u32& r2, u32& r3, u32 a) {
    asm volatile("ldmatrix.sync.aligned.m8n8.x4.shared.b16 {%0,%1,%2,%3},[%4];"
                 : "=r"(r0), "=r"(r1), "=r"(r2), "=r"(r3) : "r"(a));
}
__device__ __forceinline__ void ldsm2(u32& r0, u32& r1, u32 a) {
    asm volatile("ldmatrix.sync.aligned.m8n8.x2.shared.b16 {%0,%1},[%2];"
                 : "=r"(r0), "=r"(r1) : "r"(a));
}
__device__ __forceinline__ void mma16(float* c, const u32* a, const u32* b) {
    asm volatile("mma.sync.aligned.m16n8k16.row.col.f32.f16.f16.f32 "
                 "{%0,%1,%2,%3},{%4,%5,%6,%7},{%8,%9},{%0,%1,%2,%3};"
                 : "+f"(c[0]), "+f"(c[1]), "+f"(c[2]), "+f"(c[3])
                 : "r"(a[0]), "r"(a[1]), "r"(a[2]), "r"(a[3]), "r"(b[0]), "r"(b[1]));
}
__device__ __forceinline__ float ex2f(float x) {
    float y; asm("ex2.approx.f32 %0,%1;" : "=f"(y) : "f"(x)); return y;
}
__device__ __forceinline__ u32 h2pk(float a, float b) {
    __half2 t = __float22half2_rn(make_float2(a, b));
    return *(u32*)&t;
}
#define CPA16(d, s) asm volatile("cp.async.cg.shared.global [%0],[%1],16;" :: "r"(d), "l"(s) : "memory")
#define CPC()       asm volatile("cp.async.commit_group;" ::: "memory")
#define CPW(n)      asm volatile("cp.async.wait_group %0;" :: "n"(n) : "memory")

// =====================================================================
// fp32 -> fp16 hi/lo planar split
// =====================================================================
__global__ __launch_bounds__(256) void conv_hilo(
    const float* __restrict__ src, __half* __restrict__ hi,
    __half* __restrict__ lo, long n4)
{
    long i = (long)blockIdx.x * 256 + threadIdx.x;
    if (i >= n4) return;
    float4 v = ((const float4*)src)[i];
    float f[4] = { v.x, v.y, v.z, v.w };
    __half h[4], l[4];
#pragma unroll
    for (int e = 0; e < 4; e++) {
        h[e] = __float2half_rn(f[e]);
        l[e] = __float2half_rn(f[e] - __half2float(h[e]));
    }
    ((uint2*)hi)[i] = *(uint2*)h;
    ((uint2*)lo)[i] = *(uint2*)l;
}

// =====================================================================
// HMMA TN GEMM, fp16 hi/lo. NPROD=3: Ah*Bh+Ah*Bl+Al*Bh. NPROD=2: drop Ah*Bl
// (Blo never loaded). 128x128 tile, K-chunk 32, double-buffered, 2 CTAs/SM.
// Loop structure identical to R13/R15 passing version.
// =====================================================================
#define GSTR 40
#define GPL  5120
#define GBUF 20480
#define GM_SMEM (2 * GBUF * 2)

template <int NPROD>
__global__ __launch_bounds__(256, 2) void gemm_mma(
    const __half* __restrict__ Ahi, const __half* __restrict__ Alo,
    const __half* __restrict__ Bhi, const __half* __restrict__ Blo,
    const float* __restrict__ bias, float* __restrict__ C, int N, int K)
{
    extern __shared__ __half sh[];
    const u32 sb = smem_u32(sh);
    const int tid = threadIdx.x, w = tid >> 5, lane = tid & 31;
    const int bm = blockIdx.y * 128, bn = blockIdx.x * 128;
    const int wm = (w >> 2) * 64, wn = (w & 3) * 32;

    float acc[4][4][4];
#pragma unroll
    for (int mt = 0; mt < 4; mt++)
#pragma unroll
        for (int nt = 0; nt < 4; nt++)
#pragma unroll
            for (int r = 0; r < 4; r++) acc[mt][nt][r] = 0.f;

    const int pl = tid >> 6, lu = tid & 63, ls = lu & 3, lr0 = lu >> 2;
    const bool lskip = (NPROD < 3) && (pl == 3);
    const __half* lbase = ((pl == 0) ? Ahi : (pl == 1) ? Alo : (pl == 2) ? Bhi : Blo)
                          + (long)((pl < 2 ? bm : bn) + lr0) * K + ls * 8;
    const u32 ldst0 = (u32)((pl * GPL + lr0 * GSTR + ls * 8) * 2);
    const long lrowstride = (long)16 * K;

    const int nch = K / 32;
    if (!lskip) {
#pragma unroll
        for (int it = 0; it < 8; it++) CPA16(sb + ldst0 + it * (16 * GSTR * 2), lbase + it * lrowstride);
    }
    CPC();

    for (int c = 0; c < nch; c++) {
        if (c + 1 < nch) {
            u32 bo = (u32)(((c + 1) & 1) * GBUF * 2);
            const __half* src = lbase + (c + 1) * 32;
            if (!lskip) {
#pragma unroll
                for (int it = 0; it < 8; it++) CPA16(sb + bo + ldst0 + it * (16 * GSTR * 2), src + it * lrowstride);
            }
            CPC();
            CPW(1);
        } else {
            CPW(0);
        }
        __syncthreads();
        u32 base = sb + (u32)((c & 1) * GBUF * 2);
#pragma unroll
        for (int ks = 0; ks < 2; ks++) {
            u32 ah[4][4], al[4][4], bh[4][2], bl[4][2];
#pragma unroll
            for (int mt = 0; mt < 4; mt++) {
                u32 ra = base + (u32)(((wm + mt * 16 + (lane & 15)) * GSTR +
                                       ks * 16 + ((lane >> 4) & 1) * 8) * 2);
                ldsm4(ah[mt][0], ah[mt][1], ah[mt][2], ah[mt][3], ra);
                ldsm4(al[mt][0], al[mt][1], al[mt][2], al[mt][3], ra + GPL * 2);
            }
#pragma unroll
            for (int nt = 0; nt < 4; nt++) {
                u32 rb = base + (u32)((2 * GPL + (wn + nt * 8 + (lane & 7)) * GSTR +
                                       ks * 16 + ((lane >> 3) & 1) * 8) * 2);
                ldsm2(bh[nt][0], bh[nt][1], rb);
                if (NPROD >= 3) ldsm2(bl[nt][0], bl[nt][1], rb + GPL * 2);
            }
#pragma unroll
            for (int mt = 0; mt < 4; mt++)
#pragma unroll
                for (int nt = 0; nt < 4; nt++) {
                    mma16(acc[mt][nt], ah[mt], bh[nt]);
                    if (NPROD >= 3) mma16(acc[mt][nt], ah[mt], bl[nt]);
                    mma16(acc[mt][nt], al[mt], bh[nt]);
                }
        }
        __syncthreads();   // race guard: buf[(c-1)&1] reads done before prefetch writes in c+1
    }
    // epilogue
#pragma unroll
    for (int mt = 0; mt < 4; mt++) {
        int r0 = bm + wm + mt * 16 + (lane >> 2);
#pragma unroll
        for (int nt = 0; nt < 4; nt++) {
            int cb = bn + wn + nt * 8 + 2 * (lane & 3);
            float2 bv = *(const float2*)(bias + cb);
            float2 o0 = make_float2(acc[mt][nt][0] + bv.x, acc[mt][nt][1] + bv.y);
            float2 o1 = make_float2(acc[mt][nt][2] + bv.x, acc[mt][nt][3] + bv.y);
            *(float2*)(C + (long)r0 * N + cb) = o0;
            *(float2*)(C + (long)(r0 + 8) * N + cb) = o1;
        }
    }
}

// =====================================================================
// q/k RMS norm -> fp16 hi/lo (unchanged)
// =====================================================================
__global__ __launch_bounds__(256) void qk_norm(
    const float* __restrict__ qkv,
    const float* __restrict__ gq, const float* __restrict__ gk,
    __half* __restrict__ qhi, __half* __restrict__ qlo,
    __half* __restrict__ khi, __half* __restrict__ klo)
{
    long row = blockIdx.x;
    const float* p = qkv + row * (long)N3;
    int c = threadIdx.x * 4;
    float4 q4 = *(const float4*)(p + c);
    float4 k4 = *(const float4*)(p + DM + c);
    float sq = q4.x * q4.x + q4.y * q4.y + q4.z * q4.z + q4.w * q4.w;
    float sk = k4.x * k4.x + k4.y * k4.y + k4.z * k4.z + k4.w * k4.w;
#pragma unroll
    for (int m = 16; m; m >>= 1) {
        sq += __shfl_xor_sync(0xffffffffu, sq, m);
        sk += __shfl_xor_sync(0xffffffffu, sk, m);
    }
    __shared__ float2 ws[8];
    __shared__ float2 fac;
    int w = threadIdx.x >> 5;
    if ((threadIdx.x & 31) == 0) ws[w] = make_float2(sq, sk);
    __syncthreads();
    if (threadIdx.x == 0) {
        float a = 0.f, bsum = 0.f;
#pragma unroll
        for (int i = 0; i < 8; i++) { a += ws[i].x; bsum += ws[i].y; }
        fac = make_float2(5.770780163555851f / fmaxf(sqrtf(a), 1e-12f),   // 4*log2(e)
                          32.0f / fmaxf(sqrtf(bsum), 1e-12f));
    }
    __syncthreads();
    float fq = fac.x, fk = fac.y;
    float4 gq4 = *(const float4*)(gq + c);
    float4 gk4 = *(const float4*)(gk + c);
    float qs[4] = { q4.x * fq * gq4.x, q4.y * fq * gq4.y, q4.z * fq * gq4.z, q4.w * fq * gq4.w };
    float ks[4] = { k4.x * fk * gk4.x, k4.y * fk * gk4.y, k4.z * fk * gk4.z, k4.w * fk * gk4.w };
    __half qh[4], ql[4], kh[4], kl[4];
#pragma unroll
    for (int e = 0; e < 4; e++) {
        qh[e] = __float2half_rn(qs[e]); ql[e] = __float2half_rn(qs[e] - __half2float(qh[e]));
        kh[e] = __float2half_rn(ks[e]); kl[e] = __float2half_rn(ks[e] - __half2float(kh[e]));
    }
    long o = row * (long)DM + c;
    *(uint2*)(qhi + o) = *(uint2*)qh;  *(uint2*)(qlo + o) = *(uint2*)ql;
    *(uint2*)(khi + o) = *(uint2*)kh;  *(uint2*)(klo + o) = *(uint2*)kl;
}

// =====================================================================
// V transpose: fp32 -> SINGLE fp16 plane [(bh*64+d)][l]
// =====================================================================
#define VT_STR 136
__global__ __launch_bounds__(256) void v_trans(
    const float* __restrict__ qkv, __half* __restrict__ vthi)
{
    __shared__ __half shi[64 * VT_STR];
    int bh = blockIdx.y, b = bh >> 4, h = bh & 15;
    int l0 = blockIdx.x * 128;
    int tid = threadIdx.x;
#pragma unroll
    for (int it = 0; it < 8; it++) {
        int idx = it * 256 + tid;
        int l = idx >> 4, d4 = (idx & 15) * 4;
        float4 v = *(const float4*)(qkv + ((long)(b * LL + l0 + l)) * N3 + 2 * DM + h * 64 + d4);
        float f[4] = { v.x, v.y, v.z, v.w };
#pragma unroll
        for (int e = 0; e < 4; e++)
            shi[(d4 + e) * VT_STR + l] = __float2half_rn(f[e]);
    }
    __syncthreads();
#pragma unroll
    for (int it = 0; it < 4; it++) {
        int i = it * 256 + tid;
        int d = i >> 4, s = i & 15;
        uint4 v = *(uint4*)&shi[d * VT_STR + s * 8];
        *(uint4*)(vthi + ((long)bh * 64 + d) * LL + l0 + s * 8) = v;
    }
}

// =====================================================================
// HMMA flash attention: register-P, per-half softmax (R15 structure),
// V single fp16 -> KV buffers are 3 planes (Khi, Klo, Vhi); PV = 1 product.
// smem (halves): QHI 0, QLO 9216, KV0 18432 (13824 each), KV1 32256.
// floats: msum[2][128] @ byte 92160, lsum after. ocmb reuses KV @ 36864.
// =====================================================================
#define AKV0 18432
#define AKV1 32256
#define ARED_B 92160
#define AT_SMEM (92160 + 2048)

__global__ __launch_bounds__(256) void attn_mma(
    const __half* __restrict__ qhi, const __half* __restrict__ qlo,
    const __half* __restrict__ khi, const __half* __restrict__ klo,
    const __half* __restrict__ vthi,
    __half* __restrict__ ahi, __half* __restrict__ alo)
{
    extern __shared__ __half sh[];
    const u32 sb = smem_u32(sh);
    const int tid = threadIdx.x, w = tid >> 5, lane = tid & 31;
    const int bh = blockIdx.y, b = bh >> 4, hd = bh & 15;
    const int q0 = blockIdx.x * 128;
    const int wg = w >> 1, wn = w & 1;
    float* msum = (float*)((char*)sh + ARED_B);   // [wn][128]
    float* lsum = msum + 256;                     // [wn][128]
    float* ocmb = (float*)((char*)sh + AKV0 * 2); // [128][68]

    // Q loader
    {
        const int pl = tid >> 7, u = tid & 127, s = u & 7, r0 = u >> 3;
        const __half* qb = (pl ? qlo : qhi) + ((long)(b * LL + q0 + r0)) * DM + hd * 64 + s * 8;
        u32 d0 = sb + (u32)((pl * 9216 + r0 * 72 + s * 8) * 2);
#pragma unroll
        for (int it = 0; it < 8; it++) CPA16(d0 + it * (16 * 72 * 2), qb + (long)it * 16 * DM);
        CPC();
    }
    // KV loader: each thread handles seg (tid&7) of rows (tid>>3) and (tid>>3)+32
    // in all 3 planes (Khi, Klo, Vhi) -> 6 cp.async per chunk.
    const int krow = tid >> 3, kseg = tid & 7;
    const __half* kb0 = khi  + ((long)(b * LL + krow)) * DM + hd * 64 + kseg * 8;
    const __half* kb1 = klo  + ((long)(b * LL + krow)) * DM + hd * 64 + kseg * 8;
    const __half* vb  = vthi + ((long)(bh * 64 + krow)) * LL + kseg * 8;
    const u32 kd = (u32)((krow * 72 + kseg * 8) * 2);   // within-plane dst

#define KV_LOAD(bo, kv) do { \
    const __half* _k0 = kb0 + (long)(kv) * DM; \
    const __half* _k1 = kb1 + (long)(kv) * DM; \
    const __half* _v  = vb + (kv); \
    CPA16(sb + (bo) + kd,                 _k0); \
    CPA16(sb + (bo) + kd + 4608,          _k0 + 32 * DM); \
    CPA16(sb + (bo) + kd + 9216,          _k1); \
    CPA16(sb + (bo) + kd + 9216 + 4608,   _k1 + 32 * DM); \
    CPA16(sb + (bo) + kd + 18432,         _v); \
    CPA16(sb + (bo) + kd + 18432 + 4608,  _v + (long)32 * LL); \
} while (0)

    KV_LOAD(AKV0 * 2, 0);
    CPC();

    float o[2][8][4];
#pragma unroll
    for (int mt = 0; mt < 2; mt++)
#pragma unroll
        for (int dt = 0; dt < 8; dt++)
#pragma unroll
            for (int r = 0; r < 4; r++) o[mt][dt][r] = 0.f;
    float mr[4] = { -1e30f, -1e30f, -1e30f, -1e30f }, lr[4] = { 0.f, 0.f, 0.f, 0.f };

    for (int c = 0; c < 32; c++) {
        CPW(0);
        __syncthreads();   // single per-chunk barrier (buffer handoff + race guard)
        if (c + 1 < 32) {
            u32 bo = (u32)(((c + 1) & 1) ? AKV1 * 2 : AKV0 * 2);
            KV_LOAD(bo, (c + 1) * 64);
            CPC();
        }
        const u32 AKVB = (u32)((c & 1) ? AKV1 : AKV0);

        // ---- S = Q K^T (3 products), warp: rows wg*32..+32, keys wn*32..+32 ----
        float s[2][4][4];
#pragma unroll
        for (int mt = 0; mt < 2; mt++)
#pragma unroll
            for (int nt = 0; nt < 4; nt++)
#pragma unroll
                for (int r = 0; r < 4; r++) s[mt][nt][r] = 0.f;
#pragma unroll
        for (int ks = 0; ks < 4; ks++) {
            u32 qh_[2][4], ql_[2][4], kh_[4][2], kl_[4][2];
#pragma unroll
            for (int mt = 0; mt < 2; mt++) {
                u32 ra = sb + (u32)(((wg * 32 + mt * 16 + (lane & 15)) * 72 +
                                     ks * 16 + ((lane >> 4) & 1) * 8) * 2);
                ldsm4(qh_[mt][0], qh_[mt][1], qh_[mt][2], qh_[mt][3], ra);
                ldsm4(ql_[mt][0], ql_[mt][1], ql_[mt][2], ql_[mt][3], ra + 9216 * 2);
            }
#pragma unroll
            for (int nt = 0; nt < 4; nt++) {
                u32 rb = sb + (u32)((AKVB + (wn * 32 + nt * 8 + (lane & 7)) * 72 +
                                     ks * 16 + ((lane >> 3) & 1) * 8) * 2);
                ldsm2(kh_[nt][0], kh_[nt][1], rb);
                ldsm2(kl_[nt][0], kl_[nt][1], rb + 4608 * 2);
            }
#pragma unroll
            for (int mt = 0; mt < 2; mt++)
#pragma unroll
                for (int nt = 0; nt < 4; nt++) {
                    mma16(s[mt][nt], qh_[mt], kh_[nt]);
                    mma16(s[mt][nt], qh_[mt], kl_[nt]);
                    mma16(s[mt][nt], ql_[mt], kh_[nt]);
                }
        }

        // ---- warp-local online softmax (no cross-half exchange) ----
        float alpha[4], ssum[4];
#pragma unroll
        for (int mt = 0; mt < 2; mt++)
#pragma unroll
            for (int hh = 0; hh < 2; hh++) {
                int slot = mt * 2 + hh;
                float mx = -1e30f;
#pragma unroll
                for (int nt = 0; nt < 4; nt++) {
                    mx = fmaxf(mx, s[mt][nt][hh * 2]);
                    mx = fmaxf(mx, s[mt][nt][hh * 2 + 1]);
                }
                mx = fmaxf(mx, __shfl_xor_sync(0xffffffffu, mx, 1));
                mx = fmaxf(mx, __shfl_xor_sync(0xffffffffu, mx, 2));
                float mn = fmaxf(mr[slot], mx);
                alpha[slot] = ex2f(mr[slot] - mn);
                mr[slot] = mn;
            }
        // exponentiate in place; accumulate lane-local sums
#pragma unroll
        for (int mt = 0; mt < 2; mt++) {
            float s0 = 0.f, s1 = 0.f;
#pragma unroll
            for (int nt = 0; nt < 4; nt++) {
                s[mt][nt][0] = ex2f(s[mt][nt][0] - mr[mt * 2]);
                s[mt][nt][1] = ex2f(s[mt][nt][1] - mr[mt * 2]);
                s[mt][nt][2] = ex2f(s[mt][nt][2] - mr[mt * 2 + 1]);
                s[mt][nt][3] = ex2f(s[mt][nt][3] - mr[mt * 2 + 1]);
                s0 += s[mt][nt][0] + s[mt][nt][1];
                s1 += s[mt][nt][2] + s[mt][nt][3];
            }
            ssum[mt * 2] = s0; ssum[mt * 2 + 1] = s1;
        }
        // O rescale (before PV accumulates)
#pragma unroll
        for (int mt = 0; mt < 2; mt++)
#pragma unroll
            for (int dt = 0; dt < 8; dt++) {
                o[mt][dt][0] *= alpha[mt * 2];     o[mt][dt][1] *= alpha[mt * 2];
                o[mt][dt][2] *= alpha[mt * 2 + 1]; o[mt][dt][3] *= alpha[mt * 2 + 1];
            }
        // pack P a-frags from S c-frags
        u32 aP[2][2][4];
#pragma unroll
        for (int mt = 0; mt < 2; mt++)
#pragma unroll
            for (int ksl = 0; ksl < 2; ksl++) {
                aP[mt][ksl][0] = h2pk(s[mt][2 * ksl][0],     s[mt][2 * ksl][1]);
                aP[mt][ksl][1] = h2pk(s[mt][2 * ksl][2],     s[mt][2 * ksl][3]);
                aP[mt][ksl][2] = h2pk(s[mt][2 * ksl + 1][0], s[mt][2 * ksl + 1][1]);
                aP[mt][ksl][3] = h2pk(s[mt][2 * ksl + 1][2], s[mt][2 * ksl + 1][3]);
            }
        // ---- O += P V (single product: V hi only) ----
#pragma unroll
        for (int ksl = 0; ksl < 2; ksl++) {
            u32 vh_[8][2];
#pragma unroll
            for (int dt = 0; dt < 8; dt++) {
                u32 rb = sb + (u32)((AKVB + 9216 + (dt * 8 + (lane & 7)) * 72 +
                                     wn * 32 + ksl * 16 + ((lane >> 3) & 1) * 8) * 2);
                ldsm2(vh_[dt][0], vh_[dt][1], rb);
            }
#pragma unroll
            for (int mt = 0; mt < 2; mt++)
#pragma unroll
                for (int dt = 0; dt < 8; dt++)
                    mma16(o[mt][dt], aP[mt][ksl], vh_[dt]);
        }
        // l update (deferred shuffles; tensor pipe already busy)
#pragma unroll
        for (int slot = 0; slot < 4; slot++) {
            float sv = ssum[slot];
            sv += __shfl_xor_sync(0xffffffffu, sv, 1);
            sv += __shfl_xor_sync(0xffffffffu, sv, 2);
            lr[slot] = lr[slot] * alpha[slot] + sv;
        }
    }

    // ---- epilogue: combine halves with per-half (m, l, O) ----
    __syncthreads();   // all PV done; KV smem free
#pragma unroll
    for (int mt = 0; mt < 2; mt++)
#pragma unroll
        for (int hh = 0; hh < 2; hh++) {
            int slot = mt * 2 + hh;
            if ((lane & 3) == 0) {
                int row = wg * 32 + mt * 16 + hh * 8 + (lane >> 2);
                msum[wn * 128 + row] = mr[slot];
                lsum[wn * 128 + row] = lr[slot];
            }
        }
    if (wn == 1) {
#pragma unroll
        for (int mt = 0; mt < 2; mt++)
#pragma unroll
            for (int dt = 0; dt < 8; dt++) {
                int r = wg * 32 + mt * 16 + (lane >> 2);
                int cc = dt * 8 + (lane & 3) * 2;
                *(float2*)&ocmb[r * 68 + cc]       = make_float2(o[mt][dt][0], o[mt][dt][1]);
                *(float2*)&ocmb[(r + 8) * 68 + cc] = make_float2(o[mt][dt][2], o[mt][dt][3]);
            }
    }
    __syncthreads();
    if (wn == 0) {
        float fa0[4], fa1[4];
#pragma unroll
        for (int mt = 0; mt < 2; mt++)
#pragma unroll
            for (int hh = 0; hh < 2; hh++) {
                int slot = mt * 2 + hh;
                int row = wg * 32 + mt * 16 + hh * 8 + (lane >> 2);
                float m1 = msum[128 + row], l1 = lsum[128 + row];
                float ms = fmaxf(mr[slot], m1);
                float f0 = ex2f(mr[slot] - ms), f1 = ex2f(m1 - ms);
                float inv = 1.0f / (lr[slot] * f0 + l1 * f1);
                fa0[slot] = f0 * inv;
                fa1[slot] = f1 * inv;
            }
#pragma unroll
        for (int mt = 0; mt < 2; mt++)
#pragma unroll
            for (int dt = 0; dt < 8; dt++) {
                int r = wg * 32 + mt * 16 + (lane >> 2);
                int cc = dt * 8 + (lane & 3) * 2;
                float2 p0 = *(float2*)&ocmb[r * 68 + cc];
                float2 p1 = *(float2*)&ocmb[(r + 8) * 68 + cc];
                float v0 = o[mt][dt][0] * fa0[mt * 2]     + p0.x * fa1[mt * 2];
                float v1 = o[mt][dt][1] * fa0[mt * 2]     + p0.y * fa1[mt * 2];
                float v2 = o[mt][dt][2] * fa0[mt * 2 + 1] + p1.x * fa1[mt * 2 + 1];
                float v3 = o[mt][dt][3] * fa0[mt * 2 + 1] + p1.y * fa1[mt * 2 + 1];
                __half h0 = __float2half_rn(v0), h1 = __float2half_rn(v1);
                __half h2v = __float2half_rn(v2), h3 = __float2half_rn(v3);
                __half l0 = __float2half_rn(v0 - __half2float(h0));
                __half l1 = __float2half_rn(v1 - __half2float(h1));
                __half l2 = __float2half_rn(v2 - __half2float(h2v));
                __half l3 = __float2half_rn(v3 - __half2float(h3));
                long off0 = ((long)(b * LL + q0 + r)) * DM + hd * 64 + cc;
                long off1 = ((long)(b * LL + q0 + r + 8)) * DM + hd * 64 + cc;
                *(__half2*)(ahi + off0) = __halves2half2(h0, h1);
                *(__half2*)(alo + off0) = __halves2half2(l0, l1);
                *(__half2*)(ahi + off1) = __halves2half2(h2v, h3);
                *(__half2*)(alo + off1) = __halves2half2(l2, l3);
            }
    }
#undef KV_LOAD
}

// =====================================================================
// Final RMS norm (unchanged)
// =====================================================================
__global__ __launch_bounds__(256) void final_norm_kernel(
    const float* __restrict__ in, const float* __restrict__ g, float* __restrict__ outp)
{
    long row = blockIdx.x;
    const float* p = in + row * (long)DM;
    int c = threadIdx.x * 4;
    float4 v = *(const float4*)(p + c);
    float s = v.x * v.x + v.y * v.y + v.z * v.z + v.w * v.w;
#pragma unroll
    for (int m = 16; m; m >>= 1) s += __shfl_xor_sync(0xffffffffu, s, m);
    __shared__ float ws[8];
    __shared__ float fac;
    int w = threadIdx.x >> 5;
    if ((threadIdx.x & 31) == 0) ws[w] = s;
    __syncthreads();
    if (threadIdx.x == 0) {
        float a = 0.f;
#pragma unroll
        for (int i = 0; i < 8; i++) a += ws[i];
        fac = 32.0f / fmaxf(sqrtf(a), 1e-12f);
    }
    __syncthreads();
    float f = fac;
    float4 g4 = *(const float4*)(g + c);
    float4 o = make_float4(v.x * f * g4.x, v.y * f * g4.y, v.z * f * g4.z, v.w * f * g4.w);
    *(float4*)(outp + row * (long)DM + c) = o;
}

// =====================================================================
// launch
// =====================================================================
extern "C" void kernel_launch(void* const* d_in, const int* in_sizes, int n_in,
                              void* d_out, int out_size)
{
    const float* x    = (const float*)d_in[0];
    const float* Wqkv = (const float*)d_in[1];
    const float* bqkv = (const float*)d_in[2];
    const float* Wout = (const float*)d_in[3];
    const float* bout = (const float*)d_in[4];
    const float* gq   = (const float*)d_in[5];
    const float* gk   = (const float*)d_in[6];
    const float* gout = (const float*)d_in[7];
    float* out = (float*)d_out;

    float *qkv, *prj;
    __half *xhi, *xlo, *whi, *wlo, *wohi, *wolo;
    __half *Qhi, *Qlo, *Khi, *Klo, *Ahi, *Alo, *Vthi;
    cudaGetSymbolAddress((void**)&qkv, g_qkv);
    cudaGetSymbolAddress((void**)&prj, g_prj);
    cudaGetSymbolAddress((void**)&xhi, g_xhi);   cudaGetSymbolAddress((void**)&xlo, g_xlo);
    cudaGetSymbolAddress((void**)&whi, g_whi);   cudaGetSymbolAddress((void**)&wlo, g_wlo);
    cudaGetSymbolAddress((void**)&wohi, g_wohi); cudaGetSymbolAddress((void**)&wolo, g_wolo);
    cudaGetSymbolAddress((void**)&Qhi, g_qhi);   cudaGetSymbolAddress((void**)&Qlo, g_qlo);
    cudaGetSymbolAddress((void**)&Khi, g_khi);   cudaGetSymbolAddress((void**)&Klo, g_klo);
    cudaGetSymbolAddress((void**)&Ahi, g_ahi);   cudaGetSymbolAddress((void**)&Alo, g_alo);
    cudaGetSymbolAddress((void**)&Vthi, g_vthi);

    cudaFuncSetAttribute(gemm_mma<3>, cudaFuncAttributeMaxDynamicSharedMemorySize, GM_SMEM);
    cudaFuncSetAttribute(gemm_mma<2>, cudaFuncAttributeMaxDynamicSharedMemorySize, GM_SMEM);
    cudaFuncSetAttribute(attn_mma, cudaFuncAttributeMaxDynamicSharedMemorySize, AT_SMEM);

    // 0) fp32 -> fp16 hi/lo splits
    long n_x = (long)MR * DM / 4, n_w = (long)N3 * DM / 4, n_wo = (long)DM * DM / 4;
    conv_hilo<<<(unsigned)((n_x  + 255) / 256), 256>>>(x,    xhi,  xlo,  n_x);
    conv_hilo<<<(unsigned)((n_w  + 255) / 256), 256>>>(Wqkv, whi,  wlo,  n_w);
    conv_hilo<<<(unsigned)((n_wo + 255) / 256), 256>>>(Wout, wohi, wolo, n_wo);

    // 1) QKV projection (3 products — upstream of exp)
    gemm_mma<3><<<dim3(N3 / 128, MR / 128), 256, GM_SMEM>>>(xhi, xlo, whi, wlo, bqkv, qkv, N3, DM);

    // 2) q/k norm -> fp16 hi/lo ; V -> transposed single fp16
    qk_norm<<<MR, 256>>>(qkv, gq, gk, Qhi, Qlo, Khi, Klo);
    v_trans<<<dim3(LL / 128, BB * NH), 256>>>(qkv, Vthi);

    // 3) attention (register-P, per-half softmax, V single fp16)
    attn_mma<<<dim3(LL / 128, BB * NH), 256, AT_SMEM>>>(Qhi, Qlo, Khi, Klo, Vthi, Ahi, Alo);

    // 4) output projection (2 products — downstream of exp)
    gemm_mma<2><<<dim3(DM / 128, MR / 128), 256, GM_SMEM>>>(Ahi, Alo, wohi, wolo, bout, prj, DM, DM);

    // 5) final RMS norm -> d_out
    final_norm_kernel<<<MR, 256>>>(prj, gout, out);
}